// round 12
// baseline (speedup 1.0000x reference)
#include <cuda_runtime.h>
#include <cuda_fp16.h>
#include <cstdint>
#include <cstddef>

// Problem dims (fixed)
#define B_   16
#define TQ_  2048
#define TK_  2048
#define D_   1024

// ---------------------------------------------------------------------------
// Scratch (static __device__ arrays = sanctioned no-alloc scratch)
// fp16 hi/lo split layouts: row-major [rows, 2*K], hi in cols [0,K), lo in [K,2K).
// Alignment fp16 buffer is hi-only: [rows, TK]. encT is hi-only: [B][D, TK].
// ---------------------------------------------------------------------------
__device__ __half g_dec16 [(size_t)B_ * TQ_ * 2 * D_];   // [B*TQ, 2D]
__device__ __half g_enc16 [(size_t)B_ * TK_ * 2 * D_];   // [B*TK, 2D]
__device__ __half g_encT16[(size_t)B_ * D_  * TK_];      // [B][D, TK] hi only
__device__ __half g_keys16[(size_t)B_ * TK_ * 2 * D_];   // [B*TK, 2D]
__device__ __half g_alg16 [(size_t)B_ * TQ_ * TK_];      // [B*TQ, TK] hi only
__device__ __half g_w16T  [(size_t)D_ * 2 * D_];         // [D, 2D]

__device__ __forceinline__ uint32_t smem_u32(const void* p) {
    return (uint32_t)__cvta_generic_to_shared(p);
}

#define SW128(x) ((x) ^ (((x) >> 3) & 0x70))

// ---------------------------------------------------------------------------
// Persistent HMMA GEMM, fused hi/lo segments, flat chunk stream across tiles.
//   NSEG=3: C = hiA·hiB^T + loA·hiB^T + hiA·loB^T per chunk; stage 96KB, NS=2.
//   NSEG=1: plain C = A·B^T; stage 48KB, NS=4.
// Tile space: NX (n-tiles) x NY (m-tiles) x batch, NT total tiles.
// CTA bid processes tiles bid, bid+G, bid+2G, ... with one continuous
// cp.async pipeline; epilogue of tile t overlaps the loads of tile t+1.
// EPI=0: fp32 C.  EPI=1: bias add + hi/lo fp16 out (hi at n, lo at loOff+n).
// ---------------------------------------------------------------------------
#define BM  128
#define BN  256
#define KC  64
static constexpr int GEMM_SMEM = 196608;     // 192KB both configs

__device__ __forceinline__ void cpa16(uint32_t dst, const void* src) {
    asm volatile("cp.async.cg.shared.global [%0], [%1], 16;" :: "r"(dst), "l"(src));
}

__device__ __forceinline__ void ldsm4(uint32_t* r, uint32_t addr) {
    asm volatile("ldmatrix.sync.aligned.m8n8.x4.shared.b16 {%0,%1,%2,%3}, [%4];"
                 : "=r"(r[0]), "=r"(r[1]), "=r"(r[2]), "=r"(r[3]) : "r"(addr));
}

__device__ __forceinline__ void mma16816(float* d, const uint32_t* a,
                                         const uint32_t b0, const uint32_t b1) {
    asm volatile("mma.sync.aligned.m16n8k16.row.col.f32.f16.f16.f32 "
                 "{%0,%1,%2,%3}, {%4,%5,%6,%7}, {%8,%9}, {%0,%1,%2,%3};"
                 : "+f"(d[0]), "+f"(d[1]), "+f"(d[2]), "+f"(d[3])
                 : "r"(a[0]), "r"(a[1]), "r"(a[2]), "r"(a[3]), "r"(b0), "r"(b1));
}

// Stage tile offsets
//  NSEG=3: hiA @0 (16KB) | loA @16K (16KB) | hiB @32K (32KB) | loB @64K (32KB)
//  NSEG=1: A @0 (16KB) | B @16K (32KB)
template<int NSEG>
__device__ __forceinline__ void load_chunk(const __half* A, const __half* Bm,
                                           int lda, int ldb, int m0, int n0,
                                           int K, int kin, uint32_t stage_base,
                                           int tid) {
    const int ka = kin * KC;
    const uint32_t saH = stage_base;
    const uint32_t saL = stage_base + 16384;
    const uint32_t sbH = stage_base + (NSEG == 3 ? 32768 : 16384);
    const uint32_t sbL = stage_base + 65536;
#pragma unroll
    for (int it = 0; it < (BM * 8) / 256; ++it) {        // A: 128 rows x 8 segs
        int idx = tid + it * 256;
        int row = idx >> 3, c16 = idx & 7;
        const __half* g = A + (size_t)(m0 + row) * lda + ka + c16 * 8;
        uint32_t sw = SW128(row * 128 + c16 * 16);
        cpa16(saH + sw, g);
        if (NSEG == 3) cpa16(saL + sw, g + K);
    }
#pragma unroll
    for (int it = 0; it < (BN * 8) / 256; ++it) {        // B: 256 rows x 8 segs
        int idx = tid + it * 256;
        int row = idx >> 3, c16 = idx & 7;
        const __half* g = Bm + (size_t)(n0 + row) * ldb + ka + c16 * 8;
        uint32_t sw = SW128(row * 128 + c16 * 16);
        cpa16(sbH + sw, g);
        if (NSEG == 3) cpa16(sbL + sw, g + K);
    }
}

template<int EPI, int NSEG>
__global__ __launch_bounds__(256, 1)
void gemm_hmma(const __half* __restrict__ A, const __half* __restrict__ Bm,
               const float* __restrict__ bias,
               float* __restrict__ Cf, __half* __restrict__ Ch,
               int lda, int ldb, int ldc, int K, int loOff,
               size_t sA, size_t sB, size_t sC,
               int NX, int NY, int NT)
{
    constexpr int NSs = (NSEG == 3) ? 2 : 4;
    constexpr int STG = (NSEG == 3) ? 98304 : 49152;

    extern __shared__ __align__(1024) char smem[];
    const uint32_t smem_base = smem_u32(smem);
    const int tid = threadIdx.x, wid = tid >> 5, lid = tid & 31;

    const int bid = blockIdx.x, G = gridDim.x;
    if (bid >= NT) return;
    const int nk = K / KC;
    const int ntl = (NT - 1 - bid) / G + 1;   // tiles this CTA owns
    const int NCtot = ntl * nk;               // flat chunk count

    // warp layout: 2 (M) x 4 (N); warp tile 64x64
    const int warp_m = wid & 1;
    const int warp_n = wid >> 1;

    // ldmatrix per-lane address components
    const int aRow = warp_m * 64 + (lid & 15);
    const int aK   = (lid & 16) >> 1;       // 0 or 8
    const int bRow = warp_n * 64 + (lid & 7) + ((lid & 16) >> 1);
    const int bK   = (lid & 8);             // 0 or 8

    float acc[4][8][4];
#pragma unroll
    for (int t = 0; t < 4; ++t)
#pragma unroll
        for (int j = 0; j < 8; ++j)
#pragma unroll
            for (int c = 0; c < 4; ++c) acc[t][j][c] = 0.f;

    // flat chunk c -> issue its cp.async loads into given stage
    auto issue_load = [&](int c, int stage) {
        const int tile = bid + (c / nk) * G;
        const int n0 = (tile % NX) * BN;
        const int r  = tile / NX;
        const int m0 = (r % NY) * BM;
        const int bz = r / NY;
        load_chunk<NSEG>(A + (size_t)bz * sA, Bm + (size_t)bz * sB,
                         lda, ldb, m0, n0, K, c % nk,
                         smem_base + stage * STG, tid);
    };

    // ---- prologue: fill NSs-1 stages ----
#pragma unroll
    for (int i = 0; i < NSs - 1; ++i) {
        if (i < NCtot) issue_load(i, i);
        asm volatile("cp.async.commit_group;" ::: "memory");
    }

    for (int cc = 0; cc < NCtot; ++cc) {
        asm volatile("cp.async.wait_group %0;" :: "n"(NSs - 2));
        __syncthreads();

        // prefetch flat chunk cc+NSs-1 (may belong to the next tile)
        {
            const int cl = cc + NSs - 1;
            if (cl < NCtot) issue_load(cl, cl & (NSs - 1));
            asm volatile("cp.async.commit_group;" ::: "memory");
        }

        // ---- compute on stage cc%NSs (software-pipelined) ----
        const uint32_t st  = smem_base + (cc & (NSs - 1)) * STG;
        const uint32_t saH = st;
        const uint32_t saL = st + 16384;
        const uint32_t sbH = st + (NSEG == 3 ? 32768 : 16384);
        const uint32_t sbL = st + 65536;

        uint32_t aH[2][4][4], bH[2][4][4];
#pragma unroll
        for (int t = 0; t < 4; ++t)
            ldsm4(aH[0][t], saH + SW128((aRow + t * 16) * 128 + aK * 2));
#pragma unroll
        for (int g = 0; g < 4; ++g)
            ldsm4(bH[0][g], sbH + SW128((bRow + g * 16) * 128 + bK * 2));

#pragma unroll
        for (int ks = 0; ks < KC / 16; ++ks) {
            const int kk  = ks * 16;
            const int cur = ks & 1, nxt = cur ^ 1;
            if (NSEG == 3) {
                uint32_t aL[4][4];
#pragma unroll
                for (int t = 0; t < 4; ++t)
                    ldsm4(aL[t], saL + SW128((aRow + t * 16) * 128 + (kk + aK) * 2));
                // P0: hiA x hiB
#pragma unroll
                for (int t = 0; t < 4; ++t)
#pragma unroll
                    for (int j = 0; j < 8; ++j)
                        mma16816(acc[t][j], aH[cur][t],
                                 bH[cur][j >> 1][(j & 1) * 2], bH[cur][j >> 1][(j & 1) * 2 + 1]);
                uint32_t bL[4][4];
#pragma unroll
                for (int g = 0; g < 4; ++g)
                    ldsm4(bL[g], sbL + SW128((bRow + g * 16) * 128 + (kk + bK) * 2));
                // P1: loA x hiB
#pragma unroll
                for (int t = 0; t < 4; ++t)
#pragma unroll
                    for (int j = 0; j < 8; ++j)
                        mma16816(acc[t][j], aL[t],
                                 bH[cur][j >> 1][(j & 1) * 2], bH[cur][j >> 1][(j & 1) * 2 + 1]);
                if (ks < KC / 16 - 1) {
#pragma unroll
                    for (int t = 0; t < 4; ++t)
                        ldsm4(aH[nxt][t], saH + SW128((aRow + t * 16) * 128 + (kk + 16 + aK) * 2));
#pragma unroll
                    for (int g = 0; g < 4; ++g)
                        ldsm4(bH[nxt][g], sbH + SW128((bRow + g * 16) * 128 + (kk + 16 + bK) * 2));
                }
                // P2: hiA x loB
#pragma unroll
                for (int t = 0; t < 4; ++t)
#pragma unroll
                    for (int j = 0; j < 8; ++j)
                        mma16816(acc[t][j], aH[cur][t],
                                 bL[j >> 1][(j & 1) * 2], bL[j >> 1][(j & 1) * 2 + 1]);
            } else {
                if (ks < KC / 16 - 1) {
#pragma unroll
                    for (int t = 0; t < 4; ++t)
                        ldsm4(aH[nxt][t], saH + SW128((aRow + t * 16) * 128 + (kk + 16 + aK) * 2));
#pragma unroll
                    for (int g = 0; g < 4; ++g)
                        ldsm4(bH[nxt][g], sbH + SW128((bRow + g * 16) * 128 + (kk + 16 + bK) * 2));
                }
#pragma unroll
                for (int t = 0; t < 4; ++t)
#pragma unroll
                    for (int j = 0; j < 8; ++j)
                        mma16816(acc[t][j], aH[cur][t],
                                 bH[cur][j >> 1][(j & 1) * 2], bH[cur][j >> 1][(j & 1) * 2 + 1]);
            }
        }

        // ---- tile finished? epilogue overlaps next tile's in-flight loads ----
        if ((cc % nk) == nk - 1) {
            const int tile = bid + (cc / nk) * G;
            const int n0 = (tile % NX) * BN;
            const int r  = tile / NX;
            const int m0 = (r % NY) * BM;
            const int bz = r / NY;

            const int g8 = lid >> 2;
            const int tg = lid & 3;
#pragma unroll
            for (int t = 0; t < 4; ++t) {
                const int rbase = m0 + warp_m * 64 + t * 16 + g8;
#pragma unroll
                for (int j = 0; j < 8; ++j) {
                    const int col = n0 + warp_n * 64 + j * 8 + tg * 2;
                    if (EPI == 0) {
                        float* p0 = Cf + (size_t)bz * sC + (size_t)rbase * ldc + col;
                        float* p1 = p0 + (size_t)8 * ldc;
                        ((float2*)p0)[0] = make_float2(acc[t][j][0], acc[t][j][1]);
                        ((float2*)p1)[0] = make_float2(acc[t][j][2], acc[t][j][3]);
                    } else {
                        const float b0 = bias[col], b1 = bias[col + 1];
#pragma unroll
                        for (int hrow = 0; hrow < 2; ++hrow) {
                            const int row = rbase + hrow * 8;
                            float v0 = acc[t][j][hrow * 2 + 0] + b0;
                            float v1 = acc[t][j][hrow * 2 + 1] + b1;
                            __half h0 = __float2half_rn(v0), h1 = __float2half_rn(v1);
                            __half l0 = __float2half_rn(v0 - __half2float(h0));
                            __half l1 = __float2half_rn(v1 - __half2float(h1));
                            *(__half2*)(Ch + (size_t)row * ldc + col)         = __halves2half2(h0, h1);
                            *(__half2*)(Ch + (size_t)row * ldc + loOff + col) = __halves2half2(l0, l1);
                        }
                    }
                }
            }
            // reset accumulators for the next tile
#pragma unroll
            for (int t = 0; t < 4; ++t)
#pragma unroll
                for (int j = 0; j < 8; ++j)
#pragma unroll
                    for (int c = 0; c < 4; ++c) acc[t][j][c] = 0.f;
        }
    }
}

// ---------------------------------------------------------------------------
// fp32 [rows, C] -> fp16 [rows, 2C] hi|lo split (used for dec)
// ---------------------------------------------------------------------------
__global__ void split_rows(const float* __restrict__ in, __half* __restrict__ out,
                           int C, size_t total4)
{
    size_t i = (size_t)blockIdx.x * blockDim.x + threadIdx.x;
    if (i >= total4) return;
    const int c4 = C / 4;
    size_t r = i / c4;
    int c = (int)(i % c4) * 4;
    float4 v = ((const float4*)in)[i];
    __half h0 = __float2half_rn(v.x), h1 = __float2half_rn(v.y);
    __half h2 = __float2half_rn(v.z), h3 = __float2half_rn(v.w);
    __half l0 = __float2half_rn(v.x - __half2float(h0));
    __half l1 = __float2half_rn(v.y - __half2float(h1));
    __half l2 = __float2half_rn(v.z - __half2float(h2));
    __half l3 = __float2half_rn(v.w - __half2float(h3));
    __half* ph = out + r * (size_t)(2 * C) + c;
    ((__half2*)ph)[0] = __halves2half2(h0, h1);
    ((__half2*)ph)[1] = __halves2half2(h2, h3);
    __half* pl = ph + C;
    ((__half2*)pl)[0] = __halves2half2(l0, l1);
    ((__half2*)pl)[1] = __halves2half2(l2, l3);
}

// ---------------------------------------------------------------------------
// Fused enc conversion: one read of enc [B][TK, D] fp32 produces
//   enc16  [B*TK, 2D] hi|lo  (keys GEMM A operand)
//   encT16 [B][D, TK]  hi    (context GEMM B operand)
// ---------------------------------------------------------------------------
__global__ void enc_convert(const float* __restrict__ enc,
                            __half* __restrict__ enc16,
                            __half* __restrict__ encT16)
{
    __shared__ float t[32][33];
    const int bz = blockIdx.z;
    const float* in = enc + (size_t)bz * TK_ * D_;
    const int r0 = blockIdx.x * 32;          // TK dim
    const int c0 = blockIdx.y * 32;          // D dim
    const int tx = threadIdx.x, ty = threadIdx.y;  // 32 x 8

#pragma unroll
    for (int i = 0; i < 4; ++i)
        t[ty + i * 8][tx] = in[(size_t)(r0 + ty + i * 8) * D_ + c0 + tx];
    __syncthreads();

#pragma unroll
    for (int i = 0; i < 4; ++i) {
        const int rr = r0 + ty + i * 8;
        float v = t[ty + i * 8][tx];
        __half h = __float2half_rn(v);
        __half l = __float2half_rn(v - __half2float(h));
        __half* p = enc16 + ((size_t)bz * TK_ + rr) * (2 * D_) + c0 + tx;
        p[0]  = h;
        p[D_] = l;
    }
#pragma unroll
    for (int i = 0; i < 4; ++i) {
        const int cc = c0 + ty + i * 8;
        float v = t[tx][ty + i * 8];
        encT16[(size_t)bz * D_ * TK_ + (size_t)cc * TK_ + r0 + tx] = __float2half_rn(v);
    }
}

// ---------------------------------------------------------------------------
// W transpose + hi/lo split: in [D, D] fp32 -> out [D, 2D] fp16
// ---------------------------------------------------------------------------
__global__ void transpose_split_w(const float* __restrict__ in, __half* __restrict__ out)
{
    __shared__ float t[32][33];
    const int r0 = blockIdx.x * 32, c0 = blockIdx.y * 32;
    const int tx = threadIdx.x, ty = threadIdx.y;  // 32 x 8
#pragma unroll
    for (int i = 0; i < 4; ++i)
        t[ty + i * 8][tx] = in[(size_t)(r0 + ty + i * 8) * D_ + c0 + tx];
    __syncthreads();
#pragma unroll
    for (int i = 0; i < 4; ++i) {
        const int cc = c0 + ty + i * 8;
        float v = t[tx][ty + i * 8];
        __half h = __float2half_rn(v);
        __half l = __float2half_rn(v - __half2float(h));
        out[(size_t)cc * (2 * D_) + r0 + tx]      = h;
        out[(size_t)cc * (2 * D_) + D_ + r0 + tx] = l;
    }
}

// ---------------------------------------------------------------------------
// Row softmax over TK_=2048, in place + fp16 (hi-only) emit
// ---------------------------------------------------------------------------
__global__ void softmax2048(float* __restrict__ data, __half* __restrict__ a16)
{
    __shared__ float red[8];
    const size_t row = blockIdx.x;
    float* p = data + row * (size_t)TK_;
    const int tid = threadIdx.x, lane = tid & 31, wid = tid >> 5;

    float4 v0 = ((const float4*)p)[tid];
    float4 v1 = ((const float4*)p)[tid + 256];

    float mx = fmaxf(fmaxf(fmaxf(v0.x, v0.y), fmaxf(v0.z, v0.w)),
                     fmaxf(fmaxf(v1.x, v1.y), fmaxf(v1.z, v1.w)));
#pragma unroll
    for (int o = 16; o > 0; o >>= 1) mx = fmaxf(mx, __shfl_xor_sync(~0u, mx, o));
    if (lane == 0) red[wid] = mx;
    __syncthreads();
    mx = red[0];
#pragma unroll
    for (int w = 1; w < 8; w++) mx = fmaxf(mx, red[w]);
    __syncthreads();

    v0.x = __expf(v0.x - mx); v0.y = __expf(v0.y - mx);
    v0.z = __expf(v0.z - mx); v0.w = __expf(v0.w - mx);
    v1.x = __expf(v1.x - mx); v1.y = __expf(v1.y - mx);
    v1.z = __expf(v1.z - mx); v1.w = __expf(v1.w - mx);

    float s = v0.x + v0.y + v0.z + v0.w + v1.x + v1.y + v1.z + v1.w;
#pragma unroll
    for (int o = 16; o > 0; o >>= 1) s += __shfl_xor_sync(~0u, s, o);
    if (lane == 0) red[wid] = s;
    __syncthreads();
    s = red[0] + red[1] + red[2] + red[3] + red[4] + red[5] + red[6] + red[7];

    const float inv = 1.0f / s;
    v0.x *= inv; v0.y *= inv; v0.z *= inv; v0.w *= inv;
    v1.x *= inv; v1.y *= inv; v1.z *= inv; v1.w *= inv;

    ((float4*)p)[tid]       = v0;
    ((float4*)p)[tid + 256] = v1;

    __half* ah = a16 + row * (size_t)TK_;
    auto emit = [&](int idx, float4 v) {
        ((__half2*)(ah + idx))[0] = __halves2half2(__float2half_rn(v.x), __float2half_rn(v.y));
        ((__half2*)(ah + idx))[1] = __halves2half2(__float2half_rn(v.z), __float2half_rn(v.w));
    };
    emit(tid * 4, v0);
    emit((tid + 256) * 4, v1);
}

// ---------------------------------------------------------------------------
// kernel_launch — single stream, persistent GEMMs (grid = SM count).
// ---------------------------------------------------------------------------
extern "C" void kernel_launch(void* const* d_in, const int* in_sizes, int n_in,
                              void* d_out, int out_size)
{
    (void)in_sizes; (void)n_in; (void)out_size;

    const float* dec = (const float*)d_in[0];
    const float* enc = (const float*)d_in[1];
    const float* wk  = (const float*)d_in[2];
    const float* wb  = (const float*)d_in[3];

    float* ctx = (float*)d_out;                            // [B, TQ, D]
    float* ali = (float*)d_out + (size_t)B_ * TQ_ * D_;    // [B, TQ, TK]

    __half *dec16, *enc16, *encT16, *keys16, *alg16, *w16T;
    cudaGetSymbolAddress((void**)&dec16,  g_dec16);
    cudaGetSymbolAddress((void**)&enc16,  g_enc16);
    cudaGetSymbolAddress((void**)&encT16, g_encT16);
    cudaGetSymbolAddress((void**)&keys16, g_keys16);
    cudaGetSymbolAddress((void**)&alg16,  g_alg16);
    cudaGetSymbolAddress((void**)&w16T,   g_w16T);

    static int nsm = 0;
    if (!nsm) {
        cudaDeviceGetAttribute(&nsm, cudaDevAttrMultiProcessorCount, 0);
        if (nsm <= 0) nsm = 148;
        cudaFuncSetAttribute(gemm_hmma<0,3>, cudaFuncAttributeMaxDynamicSharedMemorySize, GEMM_SMEM);
        cudaFuncSetAttribute(gemm_hmma<1,3>, cudaFuncAttributeMaxDynamicSharedMemorySize, GEMM_SMEM);
        cudaFuncSetAttribute(gemm_hmma<0,1>, cudaFuncAttributeMaxDynamicSharedMemorySize, GEMM_SMEM);
    }

    // --- conversions ---
    {
        size_t t4 = (size_t)B_ * TQ_ * D_ / 4;
        split_rows<<<(unsigned)((t4 + 255) / 256), 256>>>(dec, dec16, D_, t4);
    }
    enc_convert<<<dim3(TK_ / 32, D_ / 32, B_), dim3(32, 8)>>>(enc, enc16, encT16);
    transpose_split_w<<<dim3(D_ / 32, D_ / 32), dim3(32, 8)>>>(wk, w16T);

    // --- keys = enc·W + bias -> keys16 hi/lo (fused 3-seg, persistent) ---
    // tiles: NX = D/BN = 4, NY = (B*TK)/BM = 256, NT = 1024 (bz always 0)
    gemm_hmma<1,3><<<nsm, 256, GEMM_SMEM>>>(
        enc16, w16T, wb, nullptr, keys16,
        2 * D_, 2 * D_, 2 * D_, D_, D_, 0, 0, 0,
        D_ / BN, (B_ * TK_) / BM, (D_ / BN) * ((B_ * TK_) / BM));

    // --- score = dec·keys^T -> ali fp32 (batched, fused 3-seg, persistent) ---
    // tiles: NX = TK/BN = 8, NY = TQ/BM = 16, NT = 8*16*16 = 2048
    gemm_hmma<0,3><<<nsm, 256, GEMM_SMEM>>>(
        dec16, keys16, nullptr, ali, nullptr,
        2 * D_, 2 * D_, TK_, D_, 0,
        (size_t)TQ_ * 2 * D_, (size_t)TK_ * 2 * D_, (size_t)TQ_ * TK_,
        TK_ / BN, TQ_ / BM, (TK_ / BN) * (TQ_ / BM) * B_);

    // --- softmax + fp16 hi emit ---
    softmax2048<<<B_ * TQ_, 256>>>(ali, alg16);

    // --- context = align·enc^T(hi) -> ctx fp32 (batched, single-pass, persistent) ---
    // tiles: NX = D/BN = 4, NY = TQ/BM = 16, NT = 4*16*16 = 1024
    gemm_hmma<0,1><<<nsm, 256, GEMM_SMEM>>>(
        alg16, encT16, nullptr, ctx, nullptr,
        TK_, TK_, D_, TK_, 0,
        (size_t)TQ_ * TK_, (size_t)D_ * TK_, (size_t)TQ_ * D_,
        D_ / BN, TQ_ / BM, (D_ / BN) * (TQ_ / BM) * B_);
}

// round 13
// speedup vs baseline: 1.0605x; 1.0605x over previous
#include <cuda_runtime.h>
#include <cuda_fp16.h>
#include <cstdint>
#include <cstddef>

// Problem dims (fixed)
#define B_   16
#define TQ_  2048
#define TK_  2048
#define D_   1024

// ---------------------------------------------------------------------------
// Scratch (static __device__ arrays = sanctioned no-alloc scratch)
// ---------------------------------------------------------------------------
__device__ __half g_dec16 [(size_t)B_ * TQ_ * 2 * D_];   // [B*TQ, 2D]
__device__ __half g_enc16 [(size_t)B_ * TK_ * 2 * D_];   // [B*TK, 2D]
__device__ __half g_encT16[(size_t)B_ * D_  * TK_];      // [B][D, TK] hi only
__device__ __half g_keys16[(size_t)B_ * TK_ * 2 * D_];   // [B*TK, 2D]
__device__ __half g_alg16 [(size_t)B_ * TQ_ * TK_];      // [B*TQ, TK] hi only
__device__ __half g_w16T  [(size_t)D_ * 2 * D_];         // [D, 2D]

__device__ __forceinline__ uint32_t smem_u32(const void* p) {
    return (uint32_t)__cvta_generic_to_shared(p);
}

#define SW128(x) ((x) ^ (((x) >> 3) & 0x70))

// ---------------------------------------------------------------------------
// HMMA GEMM, fused hi/lo segments, fine-grained ldsm/MMA interleave.
//   NSEG=3: C = hiA·hiB^T + loA·hiB^T + hiA·loB^T per chunk; stage 96KB, NS=2.
//   NSEG=1: plain C = A·B^T; stage 48KB, NS=4.
// CTA tile 128x256, K-chunk 64, 8 warps (2M x 4N), warp tile 64x64,
// mma.sync.m16n8k16. Each ldsm is issued singly between 8-MMA groups so the
// two warps per SMSP never collide in LSU bursts long enough to drain tensor.
// EPI=0: fp32 C.  EPI=1: bias add + hi/lo fp16 out (hi at n, lo at loOff+n).
// ---------------------------------------------------------------------------
#define BM  128
#define BN  256
#define KC  64
static constexpr int GEMM_SMEM = 196608;     // 192KB both configs

__device__ __forceinline__ void cpa16(uint32_t dst, const void* src) {
    asm volatile("cp.async.cg.shared.global [%0], [%1], 16;" :: "r"(dst), "l"(src));
}

__device__ __forceinline__ void ldsm4(uint32_t* r, uint32_t addr) {
    asm volatile("ldmatrix.sync.aligned.m8n8.x4.shared.b16 {%0,%1,%2,%3}, [%4];"
                 : "=r"(r[0]), "=r"(r[1]), "=r"(r[2]), "=r"(r[3]) : "r"(addr));
}

__device__ __forceinline__ void mma16816(float* d, const uint32_t* a,
                                         const uint32_t b0, const uint32_t b1) {
    asm volatile("mma.sync.aligned.m16n8k16.row.col.f32.f16.f16.f32 "
                 "{%0,%1,%2,%3}, {%4,%5,%6,%7}, {%8,%9}, {%0,%1,%2,%3};"
                 : "+f"(d[0]), "+f"(d[1]), "+f"(d[2]), "+f"(d[3])
                 : "r"(a[0]), "r"(a[1]), "r"(a[2]), "r"(a[3]), "r"(b0), "r"(b1));
}

// Stage tile offsets
//  NSEG=3: hiA @0 (16KB) | loA @16K (16KB) | hiB @32K (32KB) | loB @64K (32KB)
//  NSEG=1: A @0 (16KB) | B @16K (32KB)
template<int NSEG>
__device__ __forceinline__ void load_chunk(const __half* A, const __half* Bm,
                                           int lda, int ldb, int m0, int n0,
                                           int K, int kin, uint32_t stage_base,
                                           int tid) {
    const int ka = kin * KC;
    const uint32_t saH = stage_base;
    const uint32_t saL = stage_base + 16384;
    const uint32_t sbH = stage_base + (NSEG == 3 ? 32768 : 16384);
    const uint32_t sbL = stage_base + 65536;
#pragma unroll
    for (int it = 0; it < (BM * 8) / 256; ++it) {        // A: 128 rows x 8 segs
        int idx = tid + it * 256;
        int row = idx >> 3, c16 = idx & 7;
        const __half* g = A + (size_t)(m0 + row) * lda + ka + c16 * 8;
        uint32_t sw = SW128(row * 128 + c16 * 16);
        cpa16(saH + sw, g);
        if (NSEG == 3) cpa16(saL + sw, g + K);
    }
#pragma unroll
    for (int it = 0; it < (BN * 8) / 256; ++it) {        // B: 256 rows x 8 segs
        int idx = tid + it * 256;
        int row = idx >> 3, c16 = idx & 7;
        const __half* g = Bm + (size_t)(n0 + row) * ldb + ka + c16 * 8;
        uint32_t sw = SW128(row * 128 + c16 * 16);
        cpa16(sbH + sw, g);
        if (NSEG == 3) cpa16(sbL + sw, g + K);
    }
}

template<int EPI, int NSEG>
__global__ __launch_bounds__(256, 1)
void gemm_hmma(const __half* __restrict__ A, const __half* __restrict__ Bm,
               const float* __restrict__ bias,
               float* __restrict__ Cf, __half* __restrict__ Ch,
               int lda, int ldb, int ldc, int K, int loOff,
               size_t sA, size_t sB, size_t sC)
{
    constexpr int NSs = (NSEG == 3) ? 2 : 4;
    constexpr int STG = (NSEG == 3) ? 98304 : 49152;

    extern __shared__ __align__(1024) char smem[];
    const uint32_t smem_base = smem_u32(smem);
    const int tid = threadIdx.x, wid = tid >> 5, lid = tid & 31;
    const int bz = blockIdx.z;
    A  += (size_t)bz * sA;
    Bm += (size_t)bz * sB;

    const int m0 = blockIdx.y * BM;
    const int n0 = blockIdx.x * BN;

    const int nk = K / KC;

    // warp layout: 2 (M) x 4 (N); warp tile 64x64
    const int warp_m = wid & 1;
    const int warp_n = wid >> 1;

    float acc[4][8][4];
#pragma unroll
    for (int t = 0; t < 4; ++t)
#pragma unroll
        for (int j = 0; j < 8; ++j)
#pragma unroll
            for (int c = 0; c < 4; ++c) acc[t][j][c] = 0.f;

    // ldmatrix per-lane address components
    const int aRow = warp_m * 64 + (lid & 15);
    const int aK   = (lid & 16) >> 1;       // 0 or 8
    const int bRow = warp_n * 64 + (lid & 7) + ((lid & 16) >> 1);
    const int bK   = (lid & 8);             // 0 or 8

    // ---- prologue: fill NSs-1 stages ----
#pragma unroll
    for (int i = 0; i < NSs - 1; ++i) {
        if (i < nk) load_chunk<NSEG>(A, Bm, lda, ldb, m0, n0, K, i,
                                     smem_base + i * STG, tid);
        asm volatile("cp.async.commit_group;" ::: "memory");
    }

    for (int cc = 0; cc < nk; ++cc) {
        asm volatile("cp.async.wait_group %0;" :: "n"(NSs - 2));
        __syncthreads();

        // prefetch chunk cc+NSs-1 into the stage freed at iter cc-1
        {
            const int cl = cc + NSs - 1;
            if (cl < nk)
                load_chunk<NSEG>(A, Bm, lda, ldb, m0, n0, K, cl,
                                 smem_base + (cl & (NSs - 1)) * STG, tid);
            asm volatile("cp.async.commit_group;" ::: "memory");
        }

        // ---- compute on stage cc%NSs (fine-grained ldsm interleave) ----
        const uint32_t st  = smem_base + (cc & (NSs - 1)) * STG;
        const uint32_t saH = st;
        const uint32_t saL = st + 16384;
        const uint32_t sbH = st + (NSEG == 3 ? 32768 : 16384);
        const uint32_t sbL = st + 65536;

        uint32_t aH[2][4][4], bH[2][4][4];
        // preload kstep 0 hi fragments
#pragma unroll
        for (int t = 0; t < 4; ++t)
            ldsm4(aH[0][t], saH + SW128((aRow + t * 16) * 128 + aK * 2));
#pragma unroll
        for (int g = 0; g < 4; ++g)
            ldsm4(bH[0][g], sbH + SW128((bRow + g * 16) * 128 + bK * 2));

#pragma unroll
        for (int ks = 0; ks < KC / 16; ++ks) {
            const int kk  = ks * 16;
            const int cur = ks & 1, nxt = cur ^ 1;
            if (NSEG == 3) {
                uint32_t aL[4][4], bL[4][4];
                // Phase 0: P0 (hiA x hiB); 1 ldsm(aL) per 8-MMA group
#pragma unroll
                for (int t = 0; t < 4; ++t) {
                    ldsm4(aL[t], saL + SW128((aRow + t * 16) * 128 + (kk + aK) * 2));
#pragma unroll
                    for (int j = 0; j < 8; ++j)
                        mma16816(acc[t][j], aH[cur][t],
                                 bH[cur][j >> 1][(j & 1) * 2], bH[cur][j >> 1][(j & 1) * 2 + 1]);
                }
                // Phase 1: P1 (loA x hiB); 1 ldsm(bL) per group
#pragma unroll
                for (int t = 0; t < 4; ++t) {
                    ldsm4(bL[t], sbL + SW128((bRow + t * 16) * 128 + (kk + bK) * 2));
#pragma unroll
                    for (int j = 0; j < 8; ++j)
                        mma16816(acc[t][j], aL[t],
                                 bH[cur][j >> 1][(j & 1) * 2], bH[cur][j >> 1][(j & 1) * 2 + 1]);
                }
                // Phase 2: P2 (hiA x loB); 2 ldsm (next-kstep hi) per group
#pragma unroll
                for (int t = 0; t < 4; ++t) {
                    if (ks < KC / 16 - 1) {
                        ldsm4(aH[nxt][t], saH + SW128((aRow + t * 16) * 128 + (kk + 16 + aK) * 2));
                        ldsm4(bH[nxt][t], sbH + SW128((bRow + t * 16) * 128 + (kk + 16 + bK) * 2));
                    }
#pragma unroll
                    for (int j = 0; j < 8; ++j)
                        mma16816(acc[t][j], aH[cur][t],
                                 bL[j >> 1][(j & 1) * 2], bL[j >> 1][(j & 1) * 2 + 1]);
                }
            } else {
                // NSEG==1: 2 ldsm (next-kstep) per 8-MMA group
#pragma unroll
                for (int t = 0; t < 4; ++t) {
                    if (ks < KC / 16 - 1) {
                        ldsm4(aH[nxt][t], saH + SW128((aRow + t * 16) * 128 + (kk + 16 + aK) * 2));
                        ldsm4(bH[nxt][t], sbH + SW128((bRow + t * 16) * 128 + (kk + 16 + bK) * 2));
                    }
#pragma unroll
                    for (int j = 0; j < 8; ++j)
                        mma16816(acc[t][j], aH[cur][t],
                                 bH[cur][j >> 1][(j & 1) * 2], bH[cur][j >> 1][(j & 1) * 2 + 1]);
                }
            }
        }
    }

    // ---- epilogue ----
    const int g8 = lid >> 2;
    const int tg = lid & 3;
#pragma unroll
    for (int t = 0; t < 4; ++t) {
        const int rbase = m0 + warp_m * 64 + t * 16 + g8;
#pragma unroll
        for (int j = 0; j < 8; ++j) {
            const int col = n0 + warp_n * 64 + j * 8 + tg * 2;
            if (EPI == 0) {
                float* p0 = Cf + (size_t)bz * sC + (size_t)rbase * ldc + col;
                float* p1 = p0 + (size_t)8 * ldc;
                ((float2*)p0)[0] = make_float2(acc[t][j][0], acc[t][j][1]);
                ((float2*)p1)[0] = make_float2(acc[t][j][2], acc[t][j][3]);
            } else {
                const float b0 = bias[col], b1 = bias[col + 1];
#pragma unroll
                for (int hrow = 0; hrow < 2; ++hrow) {
                    const int row = rbase + hrow * 8;
                    float v0 = acc[t][j][hrow * 2 + 0] + b0;
                    float v1 = acc[t][j][hrow * 2 + 1] + b1;
                    __half h0 = __float2half_rn(v0), h1 = __float2half_rn(v1);
                    __half l0 = __float2half_rn(v0 - __half2float(h0));
                    __half l1 = __float2half_rn(v1 - __half2float(h1));
                    *(__half2*)(Ch + (size_t)row * ldc + col)         = __halves2half2(h0, h1);
                    *(__half2*)(Ch + (size_t)row * ldc + loOff + col) = __halves2half2(l0, l1);
                }
            }
        }
    }
}

// ---------------------------------------------------------------------------
// fp32 [rows, C] -> fp16 [rows, 2C] hi|lo split (used for dec)
// ---------------------------------------------------------------------------
__global__ void split_rows(const float* __restrict__ in, __half* __restrict__ out,
                           int C, size_t total4)
{
    size_t i = (size_t)blockIdx.x * blockDim.x + threadIdx.x;
    if (i >= total4) return;
    const int c4 = C / 4;
    size_t r = i / c4;
    int c = (int)(i % c4) * 4;
    float4 v = ((const float4*)in)[i];
    __half h0 = __float2half_rn(v.x), h1 = __float2half_rn(v.y);
    __half h2 = __float2half_rn(v.z), h3 = __float2half_rn(v.w);
    __half l0 = __float2half_rn(v.x - __half2float(h0));
    __half l1 = __float2half_rn(v.y - __half2float(h1));
    __half l2 = __float2half_rn(v.z - __half2float(h2));
    __half l3 = __float2half_rn(v.w - __half2float(h3));
    __half* ph = out + r * (size_t)(2 * C) + c;
    ((__half2*)ph)[0] = __halves2half2(h0, h1);
    ((__half2*)ph)[1] = __halves2half2(h2, h3);
    __half* pl = ph + C;
    ((__half2*)pl)[0] = __halves2half2(l0, l1);
    ((__half2*)pl)[1] = __halves2half2(l2, l3);
}

// ---------------------------------------------------------------------------
// Fused enc conversion: one read of enc [B][TK, D] fp32 produces
//   enc16  [B*TK, 2D] hi|lo  (keys GEMM A operand)
//   encT16 [B][D, TK]  hi    (context GEMM B operand)
// ---------------------------------------------------------------------------
__global__ void enc_convert(const float* __restrict__ enc,
                            __half* __restrict__ enc16,
                            __half* __restrict__ encT16)
{
    __shared__ float t[32][33];
    const int bz = blockIdx.z;
    const float* in = enc + (size_t)bz * TK_ * D_;
    const int r0 = blockIdx.x * 32;          // TK dim
    const int c0 = blockIdx.y * 32;          // D dim
    const int tx = threadIdx.x, ty = threadIdx.y;  // 32 x 8

#pragma unroll
    for (int i = 0; i < 4; ++i)
        t[ty + i * 8][tx] = in[(size_t)(r0 + ty + i * 8) * D_ + c0 + tx];
    __syncthreads();

#pragma unroll
    for (int i = 0; i < 4; ++i) {
        const int rr = r0 + ty + i * 8;
        float v = t[ty + i * 8][tx];
        __half h = __float2half_rn(v);
        __half l = __float2half_rn(v - __half2float(h));
        __half* p = enc16 + ((size_t)bz * TK_ + rr) * (2 * D_) + c0 + tx;
        p[0]  = h;
        p[D_] = l;
    }
#pragma unroll
    for (int i = 0; i < 4; ++i) {
        const int cc = c0 + ty + i * 8;
        float v = t[tx][ty + i * 8];
        encT16[(size_t)bz * D_ * TK_ + (size_t)cc * TK_ + r0 + tx] = __float2half_rn(v);
    }
}

// ---------------------------------------------------------------------------
// W transpose + hi/lo split: in [D, D] fp32 -> out [D, 2D] fp16
// ---------------------------------------------------------------------------
__global__ void transpose_split_w(const float* __restrict__ in, __half* __restrict__ out)
{
    __shared__ float t[32][33];
    const int r0 = blockIdx.x * 32, c0 = blockIdx.y * 32;
    const int tx = threadIdx.x, ty = threadIdx.y;  // 32 x 8
#pragma unroll
    for (int i = 0; i < 4; ++i)
        t[ty + i * 8][tx] = in[(size_t)(r0 + ty + i * 8) * D_ + c0 + tx];
    __syncthreads();
#pragma unroll
    for (int i = 0; i < 4; ++i) {
        const int cc = c0 + ty + i * 8;
        float v = t[tx][ty + i * 8];
        __half h = __float2half_rn(v);
        __half l = __float2half_rn(v - __half2float(h));
        out[(size_t)cc * (2 * D_) + r0 + tx]      = h;
        out[(size_t)cc * (2 * D_) + D_ + r0 + tx] = l;
    }
}

// ---------------------------------------------------------------------------
// Row softmax over TK_=2048, in place + fp16 (hi-only) emit
// ---------------------------------------------------------------------------
__global__ void softmax2048(float* __restrict__ data, __half* __restrict__ a16)
{
    __shared__ float red[8];
    const size_t row = blockIdx.x;
    float* p = data + row * (size_t)TK_;
    const int tid = threadIdx.x, lane = tid & 31, wid = tid >> 5;

    float4 v0 = ((const float4*)p)[tid];
    float4 v1 = ((const float4*)p)[tid + 256];

    float mx = fmaxf(fmaxf(fmaxf(v0.x, v0.y), fmaxf(v0.z, v0.w)),
                     fmaxf(fmaxf(v1.x, v1.y), fmaxf(v1.z, v1.w)));
#pragma unroll
    for (int o = 16; o > 0; o >>= 1) mx = fmaxf(mx, __shfl_xor_sync(~0u, mx, o));
    if (lane == 0) red[wid] = mx;
    __syncthreads();
    mx = red[0];
#pragma unroll
    for (int w = 1; w < 8; w++) mx = fmaxf(mx, red[w]);
    __syncthreads();

    v0.x = __expf(v0.x - mx); v0.y = __expf(v0.y - mx);
    v0.z = __expf(v0.z - mx); v0.w = __expf(v0.w - mx);
    v1.x = __expf(v1.x - mx); v1.y = __expf(v1.y - mx);
    v1.z = __expf(v1.z - mx); v1.w = __expf(v1.w - mx);

    float s = v0.x + v0.y + v0.z + v0.w + v1.x + v1.y + v1.z + v1.w;
#pragma unroll
    for (int o = 16; o > 0; o >>= 1) s += __shfl_xor_sync(~0u, s, o);
    if (lane == 0) red[wid] = s;
    __syncthreads();
    s = red[0] + red[1] + red[2] + red[3] + red[4] + red[5] + red[6] + red[7];

    const float inv = 1.0f / s;
    v0.x *= inv; v0.y *= inv; v0.z *= inv; v0.w *= inv;
    v1.x *= inv; v1.y *= inv; v1.z *= inv; v1.w *= inv;

    ((float4*)p)[tid]       = v0;
    ((float4*)p)[tid + 256] = v1;

    __half* ah = a16 + row * (size_t)TK_;
    auto emit = [&](int idx, float4 v) {
        ((__half2*)(ah + idx))[0] = __halves2half2(__float2half_rn(v.x), __float2half_rn(v.y));
        ((__half2*)(ah + idx))[1] = __halves2half2(__float2half_rn(v.z), __float2half_rn(v.w));
    };
    emit(tid * 4, v0);
    emit((tid + 256) * 4, v1);
}

// ---------------------------------------------------------------------------
// kernel_launch — single stream, grid-per-tile GEMMs (R10 structure).
// ---------------------------------------------------------------------------
extern "C" void kernel_launch(void* const* d_in, const int* in_sizes, int n_in,
                              void* d_out, int out_size)
{
    (void)in_sizes; (void)n_in; (void)out_size;

    const float* dec = (const float*)d_in[0];
    const float* enc = (const float*)d_in[1];
    const float* wk  = (const float*)d_in[2];
    const float* wb  = (const float*)d_in[3];

    float* ctx = (float*)d_out;                            // [B, TQ, D]
    float* ali = (float*)d_out + (size_t)B_ * TQ_ * D_;    // [B, TQ, TK]

    __half *dec16, *enc16, *encT16, *keys16, *alg16, *w16T;
    cudaGetSymbolAddress((void**)&dec16,  g_dec16);
    cudaGetSymbolAddress((void**)&enc16,  g_enc16);
    cudaGetSymbolAddress((void**)&encT16, g_encT16);
    cudaGetSymbolAddress((void**)&keys16, g_keys16);
    cudaGetSymbolAddress((void**)&alg16,  g_alg16);
    cudaGetSymbolAddress((void**)&w16T,   g_w16T);

    cudaFuncSetAttribute(gemm_hmma<0,3>, cudaFuncAttributeMaxDynamicSharedMemorySize, GEMM_SMEM);
    cudaFuncSetAttribute(gemm_hmma<1,3>, cudaFuncAttributeMaxDynamicSharedMemorySize, GEMM_SMEM);
    cudaFuncSetAttribute(gemm_hmma<0,1>, cudaFuncAttributeMaxDynamicSharedMemorySize, GEMM_SMEM);

    // --- conversions ---
    {
        size_t t4 = (size_t)B_ * TQ_ * D_ / 4;
        split_rows<<<(unsigned)((t4 + 255) / 256), 256>>>(dec, dec16, D_, t4);
    }
    enc_convert<<<dim3(TK_ / 32, D_ / 32, B_), dim3(32, 8)>>>(enc, enc16, encT16);
    transpose_split_w<<<dim3(D_ / 32, D_ / 32), dim3(32, 8)>>>(wk, w16T);

    // --- keys = enc·W + bias -> keys16 hi/lo (fused 3-seg) ---
    gemm_hmma<1,3><<<dim3(D_ / BN, (B_ * TK_) / BM, 1), 256, GEMM_SMEM>>>(
        enc16, w16T, wb, nullptr, keys16,
        2 * D_, 2 * D_, 2 * D_, D_, D_, 0, 0, 0);

    // --- score = dec·keys^T -> ali fp32 (batched, fused 3-seg) ---
    gemm_hmma<0,3><<<dim3(TK_ / BN, TQ_ / BM, B_), 256, GEMM_SMEM>>>(
        dec16, keys16, nullptr, ali, nullptr,
        2 * D_, 2 * D_, TK_, D_, 0,
        (size_t)TQ_ * 2 * D_, (size_t)TK_ * 2 * D_, (size_t)TQ_ * TK_);

    // --- softmax + fp16 hi emit ---
    softmax2048<<<B_ * TQ_, 256>>>(ali, alg16);

    // --- context = align·enc^T(hi) -> ctx fp32 (batched, single-pass) ---
    gemm_hmma<0,1><<<dim3(D_ / BN, TQ_ / BM, B_), 256, GEMM_SMEM>>>(
        alg16, encT16, nullptr, ctx, nullptr,
        TK_, TK_, D_, TK_, 0,
        (size_t)TQ_ * TK_, (size_t)D_ * TK_, (size_t)TQ_ * D_);
}

// round 15
// speedup vs baseline: 1.2398x; 1.1691x over previous
#include <cuda_runtime.h>
#include <cuda_fp16.h>
#include <cstdint>
#include <cstddef>

// Problem dims (fixed)
#define B_   16
#define TQ_  2048
#define TK_  2048
#define D_   1024

#define CAP  64
#define TAU  1e-8f

// ---------------------------------------------------------------------------
// Scratch (static __device__ arrays = sanctioned no-alloc scratch)
// ---------------------------------------------------------------------------
__device__ __half g_dec16 [(size_t)B_ * TQ_ * 2 * D_];   // [B*TQ, 2D]
__device__ __half g_enc16 [(size_t)B_ * TK_ * 2 * D_];   // [B*TK, 2D]
__device__ __half g_keys16[(size_t)B_ * TK_ * 2 * D_];   // [B*TK, 2D]
__device__ __half g_w16T  [(size_t)D_ * 2 * D_];         // [D, 2D]
__device__ int    g_sp_idx[(size_t)B_ * TQ_ * CAP];      // sparse indices
__device__ float  g_sp_w  [(size_t)B_ * TQ_ * CAP];      // sparse weights
__device__ int    g_sp_cnt[(size_t)B_ * TQ_];            // entry counts

__device__ __forceinline__ uint32_t smem_u32(const void* p) {
    return (uint32_t)__cvta_generic_to_shared(p);
}

#define SW128(x) ((x) ^ (((x) >> 3) & 0x70))

// ---------------------------------------------------------------------------
// HMMA GEMM, fused hi/lo segments (R13 proven inner loop).
//   NSEG=3: C = hiA·hiB^T + loA·hiB^T + hiA·loB^T per chunk; stage 96KB, NS=2.
// CTA tile 128x256, K-chunk 64, 8 warps (2M x 4N), warp tile 64x64.
// EPI=0: fp32 C.  EPI=1: bias add + hi/lo fp16 out (hi at n, lo at loOff+n).
// ---------------------------------------------------------------------------
#define BM  128
#define BN  256
#define KC  64
static constexpr int GEMM_SMEM = 196608;

__device__ __forceinline__ void cpa16(uint32_t dst, const void* src) {
    asm volatile("cp.async.cg.shared.global [%0], [%1], 16;" :: "r"(dst), "l"(src));
}

__device__ __forceinline__ void ldsm4(uint32_t* r, uint32_t addr) {
    asm volatile("ldmatrix.sync.aligned.m8n8.x4.shared.b16 {%0,%1,%2,%3}, [%4];"
                 : "=r"(r[0]), "=r"(r[1]), "=r"(r[2]), "=r"(r[3]) : "r"(addr));
}

__device__ __forceinline__ void mma16816(float* d, const uint32_t* a,
                                         const uint32_t b0, const uint32_t b1) {
    asm volatile("mma.sync.aligned.m16n8k16.row.col.f32.f16.f16.f32 "
                 "{%0,%1,%2,%3}, {%4,%5,%6,%7}, {%8,%9}, {%0,%1,%2,%3};"
                 : "+f"(d[0]), "+f"(d[1]), "+f"(d[2]), "+f"(d[3])
                 : "r"(a[0]), "r"(a[1]), "r"(a[2]), "r"(a[3]), "r"(b0), "r"(b1));
}

template<int NSEG>
__device__ __forceinline__ void load_chunk(const __half* A, const __half* Bm,
                                           int lda, int ldb, int m0, int n0,
                                           int K, int kin, uint32_t stage_base,
                                           int tid) {
    const int ka = kin * KC;
    const uint32_t saH = stage_base;
    const uint32_t saL = stage_base + 16384;
    const uint32_t sbH = stage_base + (NSEG == 3 ? 32768 : 16384);
    const uint32_t sbL = stage_base + 65536;
#pragma unroll
    for (int it = 0; it < (BM * 8) / 256; ++it) {
        int idx = tid + it * 256;
        int row = idx >> 3, c16 = idx & 7;
        const __half* g = A + (size_t)(m0 + row) * lda + ka + c16 * 8;
        uint32_t sw = SW128(row * 128 + c16 * 16);
        cpa16(saH + sw, g);
        if (NSEG == 3) cpa16(saL + sw, g + K);
    }
#pragma unroll
    for (int it = 0; it < (BN * 8) / 256; ++it) {
        int idx = tid + it * 256;
        int row = idx >> 3, c16 = idx & 7;
        const __half* g = Bm + (size_t)(n0 + row) * ldb + ka + c16 * 8;
        uint32_t sw = SW128(row * 128 + c16 * 16);
        cpa16(sbH + sw, g);
        if (NSEG == 3) cpa16(sbL + sw, g + K);
    }
}

template<int EPI, int NSEG>
__global__ __launch_bounds__(256, 1)
void gemm_hmma(const __half* __restrict__ A, const __half* __restrict__ Bm,
               const float* __restrict__ bias,
               float* __restrict__ Cf, __half* __restrict__ Ch,
               int lda, int ldb, int ldc, int K, int loOff,
               size_t sA, size_t sB, size_t sC)
{
    constexpr int NSs = (NSEG == 3) ? 2 : 4;
    constexpr int STG = (NSEG == 3) ? 98304 : 49152;

    extern __shared__ __align__(1024) char smem[];
    const uint32_t smem_base = smem_u32(smem);
    const int tid = threadIdx.x, wid = tid >> 5, lid = tid & 31;
    const int bz = blockIdx.z;
    A  += (size_t)bz * sA;
    Bm += (size_t)bz * sB;

    const int m0 = blockIdx.y * BM;
    const int n0 = blockIdx.x * BN;

    const int nk = K / KC;

    const int warp_m = wid & 1;
    const int warp_n = wid >> 1;

    float acc[4][8][4];
#pragma unroll
    for (int t = 0; t < 4; ++t)
#pragma unroll
        for (int j = 0; j < 8; ++j)
#pragma unroll
            for (int c = 0; c < 4; ++c) acc[t][j][c] = 0.f;

    const int aRow = warp_m * 64 + (lid & 15);
    const int aK   = (lid & 16) >> 1;
    const int bRow = warp_n * 64 + (lid & 7) + ((lid & 16) >> 1);
    const int bK   = (lid & 8);

#pragma unroll
    for (int i = 0; i < NSs - 1; ++i) {
        if (i < nk) load_chunk<NSEG>(A, Bm, lda, ldb, m0, n0, K, i,
                                     smem_base + i * STG, tid);
        asm volatile("cp.async.commit_group;" ::: "memory");
    }

    for (int cc = 0; cc < nk; ++cc) {
        asm volatile("cp.async.wait_group %0;" :: "n"(NSs - 2));
        __syncthreads();

        {
            const int cl = cc + NSs - 1;
            if (cl < nk)
                load_chunk<NSEG>(A, Bm, lda, ldb, m0, n0, K, cl,
                                 smem_base + (cl & (NSs - 1)) * STG, tid);
            asm volatile("cp.async.commit_group;" ::: "memory");
        }

        const uint32_t st  = smem_base + (cc & (NSs - 1)) * STG;
        const uint32_t saH = st;
        const uint32_t saL = st + 16384;
        const uint32_t sbH = st + (NSEG == 3 ? 32768 : 16384);
        const uint32_t sbL = st + 65536;

        uint32_t aH[2][4][4], bH[2][4][4];
#pragma unroll
        for (int t = 0; t < 4; ++t)
            ldsm4(aH[0][t], saH + SW128((aRow + t * 16) * 128 + aK * 2));
#pragma unroll
        for (int g = 0; g < 4; ++g)
            ldsm4(bH[0][g], sbH + SW128((bRow + g * 16) * 128 + bK * 2));

#pragma unroll
        for (int ks = 0; ks < KC / 16; ++ks) {
            const int kk  = ks * 16;
            const int cur = ks & 1, nxt = cur ^ 1;
            if (NSEG == 3) {
                uint32_t aL[4][4], bL[4][4];
#pragma unroll
                for (int t = 0; t < 4; ++t) {
                    ldsm4(aL[t], saL + SW128((aRow + t * 16) * 128 + (kk + aK) * 2));
#pragma unroll
                    for (int j = 0; j < 8; ++j)
                        mma16816(acc[t][j], aH[cur][t],
                                 bH[cur][j >> 1][(j & 1) * 2], bH[cur][j >> 1][(j & 1) * 2 + 1]);
                }
#pragma unroll
                for (int t = 0; t < 4; ++t) {
                    ldsm4(bL[t], sbL + SW128((bRow + t * 16) * 128 + (kk + bK) * 2));
#pragma unroll
                    for (int j = 0; j < 8; ++j)
                        mma16816(acc[t][j], aL[t],
                                 bH[cur][j >> 1][(j & 1) * 2], bH[cur][j >> 1][(j & 1) * 2 + 1]);
                }
#pragma unroll
                for (int t = 0; t < 4; ++t) {
                    if (ks < KC / 16 - 1) {
                        ldsm4(aH[nxt][t], saH + SW128((aRow + t * 16) * 128 + (kk + 16 + aK) * 2));
                        ldsm4(bH[nxt][t], sbH + SW128((bRow + t * 16) * 128 + (kk + 16 + bK) * 2));
                    }
#pragma unroll
                    for (int j = 0; j < 8; ++j)
                        mma16816(acc[t][j], aH[cur][t],
                                 bL[j >> 1][(j & 1) * 2], bL[j >> 1][(j & 1) * 2 + 1]);
                }
            } else {
#pragma unroll
                for (int t = 0; t < 4; ++t) {
                    if (ks < KC / 16 - 1) {
                        ldsm4(aH[nxt][t], saH + SW128((aRow + t * 16) * 128 + (kk + 16 + aK) * 2));
                        ldsm4(bH[nxt][t], sbH + SW128((bRow + t * 16) * 128 + (kk + 16 + bK) * 2));
                    }
#pragma unroll
                    for (int j = 0; j < 8; ++j)
                        mma16816(acc[t][j], aH[cur][t],
                                 bH[cur][j >> 1][(j & 1) * 2], bH[cur][j >> 1][(j & 1) * 2 + 1]);
                }
            }
        }
    }

    // ---- epilogue ----
    const int g8 = lid >> 2;
    const int tg = lid & 3;
#pragma unroll
    for (int t = 0; t < 4; ++t) {
        const int rbase = m0 + warp_m * 64 + t * 16 + g8;
#pragma unroll
        for (int j = 0; j < 8; ++j) {
            const int col = n0 + warp_n * 64 + j * 8 + tg * 2;
            if (EPI == 0) {
                float* p0 = Cf + (size_t)bz * sC + (size_t)rbase * ldc + col;
                float* p1 = p0 + (size_t)8 * ldc;
                ((float2*)p0)[0] = make_float2(acc[t][j][0], acc[t][j][1]);
                ((float2*)p1)[0] = make_float2(acc[t][j][2], acc[t][j][3]);
            } else {
                const float b0 = bias[col], b1 = bias[col + 1];
#pragma unroll
                for (int hrow = 0; hrow < 2; ++hrow) {
                    const int row = rbase + hrow * 8;
                    float v0 = acc[t][j][hrow * 2 + 0] + b0;
                    float v1 = acc[t][j][hrow * 2 + 1] + b1;
                    __half h0 = __float2half_rn(v0), h1 = __float2half_rn(v1);
                    __half l0 = __float2half_rn(v0 - __half2float(h0));
                    __half l1 = __float2half_rn(v1 - __half2float(h1));
                    *(__half2*)(Ch + (size_t)row * ldc + col)         = __halves2half2(h0, h1);
                    *(__half2*)(Ch + (size_t)row * ldc + loOff + col) = __halves2half2(l0, l1);
                }
            }
        }
    }
}

// ---------------------------------------------------------------------------
// fp32 [rows, C] -> fp16 [rows, 2C] hi|lo split (dec and enc)
// ---------------------------------------------------------------------------
__global__ void split_rows(const float* __restrict__ in, __half* __restrict__ out,
                           int C, size_t total4)
{
    size_t i = (size_t)blockIdx.x * blockDim.x + threadIdx.x;
    if (i >= total4) return;
    const int c4 = C / 4;
    size_t r = i / c4;
    int c = (int)(i % c4) * 4;
    float4 v = ((const float4*)in)[i];
    __half h0 = __float2half_rn(v.x), h1 = __float2half_rn(v.y);
    __half h2 = __float2half_rn(v.z), h3 = __float2half_rn(v.w);
    __half l0 = __float2half_rn(v.x - __half2float(h0));
    __half l1 = __float2half_rn(v.y - __half2float(h1));
    __half l2 = __float2half_rn(v.z - __half2float(h2));
    __half l3 = __float2half_rn(v.w - __half2float(h3));
    __half* ph = out + r * (size_t)(2 * C) + c;
    ((__half2*)ph)[0] = __halves2half2(h0, h1);
    ((__half2*)ph)[1] = __halves2half2(h2, h3);
    __half* pl = ph + C;
    ((__half2*)pl)[0] = __halves2half2(l0, l1);
    ((__half2*)pl)[1] = __halves2half2(l2, l3);
}

// ---------------------------------------------------------------------------
// W transpose + hi/lo split: in [D, D] fp32 -> out [D, 2D] fp16
// ---------------------------------------------------------------------------
__global__ void transpose_split_w(const float* __restrict__ in, __half* __restrict__ out)
{
    __shared__ float t[32][33];
    const int r0 = blockIdx.x * 32, c0 = blockIdx.y * 32;
    const int tx = threadIdx.x, ty = threadIdx.y;  // 32 x 8
#pragma unroll
    for (int i = 0; i < 4; ++i)
        t[ty + i * 8][tx] = in[(size_t)(r0 + ty + i * 8) * D_ + c0 + tx];
    __syncthreads();
#pragma unroll
    for (int i = 0; i < 4; ++i) {
        const int cc = c0 + ty + i * 8;
        float v = t[tx][ty + i * 8];
        __half h = __float2half_rn(v);
        __half l = __float2half_rn(v - __half2float(h));
        out[(size_t)cc * (2 * D_) + r0 + tx]      = h;
        out[(size_t)cc * (2 * D_) + D_ + r0 + tx] = l;
    }
}

// ---------------------------------------------------------------------------
// Row softmax over TK_=2048, in place + sparse (idx, weight) list emission.
// Entries with p > TAU are appended in deterministic k-order (block scan).
// ---------------------------------------------------------------------------
__global__ void softmax2048(float* __restrict__ data,
                            int* __restrict__ sp_idx, float* __restrict__ sp_w,
                            int* __restrict__ sp_cnt)
{
    __shared__ float red[8];
    __shared__ int   wsum[8];
    __shared__ int   carry;
    const size_t row = blockIdx.x;
    float* p = data + row * (size_t)TK_;
    const int tid = threadIdx.x, lane = tid & 31, wid = tid >> 5;

    float4 v0 = ((const float4*)p)[tid];
    float4 v1 = ((const float4*)p)[tid + 256];

    float mx = fmaxf(fmaxf(fmaxf(v0.x, v0.y), fmaxf(v0.z, v0.w)),
                     fmaxf(fmaxf(v1.x, v1.y), fmaxf(v1.z, v1.w)));
#pragma unroll
    for (int o = 16; o > 0; o >>= 1) mx = fmaxf(mx, __shfl_xor_sync(~0u, mx, o));
    if (lane == 0) red[wid] = mx;
    __syncthreads();
    mx = red[0];
#pragma unroll
    for (int w = 1; w < 8; w++) mx = fmaxf(mx, red[w]);
    __syncthreads();

    v0.x = __expf(v0.x - mx); v0.y = __expf(v0.y - mx);
    v0.z = __expf(v0.z - mx); v0.w = __expf(v0.w - mx);
    v1.x = __expf(v1.x - mx); v1.y = __expf(v1.y - mx);
    v1.z = __expf(v1.z - mx); v1.w = __expf(v1.w - mx);

    float s = v0.x + v0.y + v0.z + v0.w + v1.x + v1.y + v1.z + v1.w;
#pragma unroll
    for (int o = 16; o > 0; o >>= 1) s += __shfl_xor_sync(~0u, s, o);
    if (lane == 0) red[wid] = s;
    __syncthreads();
    s = red[0] + red[1] + red[2] + red[3] + red[4] + red[5] + red[6] + red[7];

    const float inv = 1.0f / s;
    v0.x *= inv; v0.y *= inv; v0.z *= inv; v0.w *= inv;
    v1.x *= inv; v1.y *= inv; v1.z *= inv; v1.w *= inv;

    ((float4*)p)[tid]       = v0;
    ((float4*)p)[tid + 256] = v1;

    // ---- sparse emission (deterministic order) ----
    if (tid == 0) carry = 0;
    __syncthreads();

    int* rIdx = sp_idx + row * CAP;
    float* rW = sp_w   + row * CAP;

    auto emit = [&](float4 v, int kbase) {
        float vals[4] = {v.x, v.y, v.z, v.w};
        int cnt = 0;
#pragma unroll
        for (int i = 0; i < 4; ++i) cnt += (vals[i] > TAU) ? 1 : 0;
        // inclusive warp scan of cnt
        int inc = cnt;
#pragma unroll
        for (int o = 1; o < 32; o <<= 1) {
            int n = __shfl_up_sync(~0u, inc, o);
            if (lane >= o) inc += n;
        }
        if (lane == 31) wsum[wid] = inc;
        __syncthreads();
        int wbase = 0;
#pragma unroll
        for (int w = 0; w < 8; ++w) if (w < wid) wbase += wsum[w];
        int base = carry + wbase + inc - cnt;   // exclusive offset for this thread
        int o = 0;
#pragma unroll
        for (int i = 0; i < 4; ++i) {
            if (vals[i] > TAU) {
                int pos = base + o; ++o;
                if (pos < CAP) { rIdx[pos] = kbase + i; rW[pos] = vals[i]; }
            }
        }
        __syncthreads();
        if (tid == 0) {
            int t = 0;
#pragma unroll
            for (int w = 0; w < 8; ++w) t += wsum[w];
            carry += t;
        }
        __syncthreads();
    };

    emit(v0, tid * 4);
    emit(v1, (tid + 256) * 4);

    if (tid == 0) sp_cnt[row] = carry;
}

// ---------------------------------------------------------------------------
// Sparse context: ctx[row,:] = sum_e w_e * enc[b, k_e, :]  (fp32 exact).
// One block (256 thr) per row; 4 floats (1 float4) per thread.
// Dense fallback (exact) if count > CAP.
// ---------------------------------------------------------------------------
__global__ __launch_bounds__(256)
void ctx_sparse(const float* __restrict__ enc, const float* __restrict__ ali,
                const int* __restrict__ sp_cnt, const int* __restrict__ sp_idx,
                const float* __restrict__ sp_w, float* __restrict__ ctx)
{
    const int row = blockIdx.x;               // 0..B*TQ-1
    const int b   = row / TQ_;
    const int tid = threadIdx.x;
    const float* encB = enc + (size_t)b * TK_ * D_;

    float4 acc = make_float4(0.f, 0.f, 0.f, 0.f);
    const int cnt = sp_cnt[row];

    if (cnt <= CAP) {
        const int* rIdx = sp_idx + (size_t)row * CAP;
        const float* rW = sp_w + (size_t)row * CAP;
        for (int e = 0; e < cnt; ++e) {
            const int k = rIdx[e];
            const float w = rW[e];
            float4 ev = ((const float4*)(encB + (size_t)k * D_))[tid];
            acc.x += w * ev.x; acc.y += w * ev.y;
            acc.z += w * ev.z; acc.w += w * ev.w;
        }
    } else {
        // exact dense fallback (never expected; correctness armor)
        const float* arow = ali + (size_t)row * TK_;
        for (int k = 0; k < TK_; ++k) {
            const float w = arow[k];
            if (w > TAU) {
                float4 ev = ((const float4*)(encB + (size_t)k * D_))[tid];
                acc.x += w * ev.x; acc.y += w * ev.y;
                acc.z += w * ev.z; acc.w += w * ev.w;
            }
        }
    }
    ((float4*)(ctx + (size_t)row * D_))[tid] = acc;
}

// ---------------------------------------------------------------------------
// kernel_launch — single stream.
// dec split -> enc split -> W split -> keys GEMM -> score GEMM
//   -> softmax (+sparse lists) -> sparse context gather
// ---------------------------------------------------------------------------
extern "C" void kernel_launch(void* const* d_in, const int* in_sizes, int n_in,
                              void* d_out, int out_size)
{
    (void)in_sizes; (void)n_in; (void)out_size;

    const float* dec = (const float*)d_in[0];
    const float* enc = (const float*)d_in[1];
    const float* wk  = (const float*)d_in[2];
    const float* wb  = (const float*)d_in[3];

    float* ctx = (float*)d_out;                            // [B, TQ, D]
    float* ali = (float*)d_out + (size_t)B_ * TQ_ * D_;    // [B, TQ, TK]

    __half *dec16, *enc16, *keys16, *w16T;
    int *sp_idx, *sp_cnt;
    float *sp_w;
    cudaGetSymbolAddress((void**)&dec16,  g_dec16);
    cudaGetSymbolAddress((void**)&enc16,  g_enc16);
    cudaGetSymbolAddress((void**)&keys16, g_keys16);
    cudaGetSymbolAddress((void**)&w16T,   g_w16T);
    cudaGetSymbolAddress((void**)&sp_idx, g_sp_idx);
    cudaGetSymbolAddress((void**)&sp_w,   g_sp_w);
    cudaGetSymbolAddress((void**)&sp_cnt, g_sp_cnt);

    cudaFuncSetAttribute(gemm_hmma<0,3>, cudaFuncAttributeMaxDynamicSharedMemorySize, GEMM_SMEM);
    cudaFuncSetAttribute(gemm_hmma<1,3>, cudaFuncAttributeMaxDynamicSharedMemorySize, GEMM_SMEM);

    // --- conversions ---
    {
        size_t t4 = (size_t)B_ * TQ_ * D_ / 4;
        split_rows<<<(unsigned)((t4 + 255) / 256), 256>>>(dec, dec16, D_, t4);
        split_rows<<<(unsigned)((t4 + 255) / 256), 256>>>(enc, enc16, D_, t4);
    }
    transpose_split_w<<<dim3(D_ / 32, D_ / 32), dim3(32, 8)>>>(wk, w16T);

    // --- keys = enc·W + bias -> keys16 hi/lo (fused 3-seg) ---
    gemm_hmma<1,3><<<dim3(D_ / BN, (B_ * TK_) / BM, 1), 256, GEMM_SMEM>>>(
        enc16, w16T, wb, nullptr, keys16,
        2 * D_, 2 * D_, 2 * D_, D_, D_, 0, 0, 0);

    // --- score = dec·keys^T -> ali fp32 (batched, fused 3-seg) ---
    gemm_hmma<0,3><<<dim3(TK_ / BN, TQ_ / BM, B_), 256, GEMM_SMEM>>>(
        dec16, keys16, nullptr, ali, nullptr,
        2 * D_, 2 * D_, TK_, D_, 0,
        (size_t)TQ_ * 2 * D_, (size_t)TK_ * 2 * D_, (size_t)TQ_ * TK_);

    // --- softmax + sparse list emission ---
    softmax2048<<<B_ * TQ_, 256>>>(ali, sp_idx, sp_w, sp_cnt);

    // --- context = sparse gather over enc (fp32 exact) ---
    ctx_sparse<<<B_ * TQ_, 256>>>(enc, ali, sp_cnt, sp_idx, sp_w, ctx);
}

// round 16
// speedup vs baseline: 1.4942x; 1.2052x over previous
#include <cuda_runtime.h>
#include <cuda_fp16.h>
#include <cstdint>
#include <cstddef>

// Problem dims (fixed)
#define B_   16
#define TQ_  2048
#define TK_  2048
#define D_   1024

#define CAP     64          // sparse-context list capacity (p > TAU)
#define TAU     1e-8f
#define MARGIN  23.0f       // candidate screen margin (18.42 + guard)

// ---------------------------------------------------------------------------
// Scratch (static __device__ arrays = sanctioned no-alloc scratch)
// ---------------------------------------------------------------------------
__device__ __half g_dec16 [(size_t)B_ * TQ_ * 2 * D_];   // [B*TQ, 2D]
__device__ __half g_enc16 [(size_t)B_ * TK_ * 2 * D_];   // [B*TK, 2D]
__device__ __half g_keys16[(size_t)B_ * TK_ * 2 * D_];   // [B*TK, 2D]
__device__ __half g_w16T  [(size_t)D_ * 2 * D_];         // [D, 2D]
__device__ int    g_sp_idx[(size_t)B_ * TQ_ * CAP];
__device__ float  g_sp_w  [(size_t)B_ * TQ_ * CAP];
__device__ int    g_sp_cnt[(size_t)B_ * TQ_];

__device__ __forceinline__ uint32_t smem_u32(const void* p) {
    return (uint32_t)__cvta_generic_to_shared(p);
}

#define SW128(x) ((x) ^ (((x) >> 3) & 0x70))

// ---------------------------------------------------------------------------
// HMMA GEMM, fused hi/lo segments (R13 proven inner loop).
//   NSEG=3: C = hiA·hiB^T + loA·hiB^T + hiA·loB^T; stage 96KB, NS=2.
//   NSEG=1: plain C = A·B^T (hi halves); stage 48KB, NS=4.
// CTA tile 128x256, K-chunk 64, 8 warps (2M x 4N), warp tile 64x64.
// EPI=0: fp32 C.  EPI=1: bias add + hi/lo fp16 out (hi at n, lo at loOff+n).
// ---------------------------------------------------------------------------
#define BM  128
#define BN  256
#define KC  64
static constexpr int GEMM_SMEM = 196608;

__device__ __forceinline__ void cpa16(uint32_t dst, const void* src) {
    asm volatile("cp.async.cg.shared.global [%0], [%1], 16;" :: "r"(dst), "l"(src));
}

__device__ __forceinline__ void ldsm4(uint32_t* r, uint32_t addr) {
    asm volatile("ldmatrix.sync.aligned.m8n8.x4.shared.b16 {%0,%1,%2,%3}, [%4];"
                 : "=r"(r[0]), "=r"(r[1]), "=r"(r[2]), "=r"(r[3]) : "r"(addr));
}

__device__ __forceinline__ void mma16816(float* d, const uint32_t* a,
                                         const uint32_t b0, const uint32_t b1) {
    asm volatile("mma.sync.aligned.m16n8k16.row.col.f32.f16.f16.f32 "
                 "{%0,%1,%2,%3}, {%4,%5,%6,%7}, {%8,%9}, {%0,%1,%2,%3};"
                 : "+f"(d[0]), "+f"(d[1]), "+f"(d[2]), "+f"(d[3])
                 : "r"(a[0]), "r"(a[1]), "r"(a[2]), "r"(a[3]), "r"(b0), "r"(b1));
}

template<int NSEG>
__device__ __forceinline__ void load_chunk(const __half* A, const __half* Bm,
                                           int lda, int ldb, int m0, int n0,
                                           int K, int kin, uint32_t stage_base,
                                           int tid) {
    const int ka = kin * KC;
    const uint32_t saH = stage_base;
    const uint32_t saL = stage_base + 16384;
    const uint32_t sbH = stage_base + (NSEG == 3 ? 32768 : 16384);
    const uint32_t sbL = stage_base + 65536;
#pragma unroll
    for (int it = 0; it < (BM * 8) / 256; ++it) {
        int idx = tid + it * 256;
        int row = idx >> 3, c16 = idx & 7;
        const __half* g = A + (size_t)(m0 + row) * lda + ka + c16 * 8;
        uint32_t sw = SW128(row * 128 + c16 * 16);
        cpa16(saH + sw, g);
        if (NSEG == 3) cpa16(saL + sw, g + K);
    }
#pragma unroll
    for (int it = 0; it < (BN * 8) / 256; ++it) {
        int idx = tid + it * 256;
        int row = idx >> 3, c16 = idx & 7;
        const __half* g = Bm + (size_t)(n0 + row) * ldb + ka + c16 * 8;
        uint32_t sw = SW128(row * 128 + c16 * 16);
        cpa16(sbH + sw, g);
        if (NSEG == 3) cpa16(sbL + sw, g + K);
    }
}

template<int EPI, int NSEG>
__global__ __launch_bounds__(256, 1)
void gemm_hmma(const __half* __restrict__ A, const __half* __restrict__ Bm,
               const float* __restrict__ bias,
               float* __restrict__ Cf, __half* __restrict__ Ch,
               int lda, int ldb, int ldc, int K, int loOff,
               size_t sA, size_t sB, size_t sC)
{
    constexpr int NSs = (NSEG == 3) ? 2 : 4;
    constexpr int STG = (NSEG == 3) ? 98304 : 49152;

    extern __shared__ __align__(1024) char smem[];
    const uint32_t smem_base = smem_u32(smem);
    const int tid = threadIdx.x, wid = tid >> 5, lid = tid & 31;
    const int bz = blockIdx.z;
    A  += (size_t)bz * sA;
    Bm += (size_t)bz * sB;

    const int m0 = blockIdx.y * BM;
    const int n0 = blockIdx.x * BN;

    const int nk = K / KC;

    const int warp_m = wid & 1;
    const int warp_n = wid >> 1;

    float acc[4][8][4];
#pragma unroll
    for (int t = 0; t < 4; ++t)
#pragma unroll
        for (int j = 0; j < 8; ++j)
#pragma unroll
            for (int c = 0; c < 4; ++c) acc[t][j][c] = 0.f;

    const int aRow = warp_m * 64 + (lid & 15);
    const int aK   = (lid & 16) >> 1;
    const int bRow = warp_n * 64 + (lid & 7) + ((lid & 16) >> 1);
    const int bK   = (lid & 8);

#pragma unroll
    for (int i = 0; i < NSs - 1; ++i) {
        if (i < nk) load_chunk<NSEG>(A, Bm, lda, ldb, m0, n0, K, i,
                                     smem_base + i * STG, tid);
        asm volatile("cp.async.commit_group;" ::: "memory");
    }

    for (int cc = 0; cc < nk; ++cc) {
        asm volatile("cp.async.wait_group %0;" :: "n"(NSs - 2));
        __syncthreads();

        {
            const int cl = cc + NSs - 1;
            if (cl < nk)
                load_chunk<NSEG>(A, Bm, lda, ldb, m0, n0, K, cl,
                                 smem_base + (cl & (NSs - 1)) * STG, tid);
            asm volatile("cp.async.commit_group;" ::: "memory");
        }

        const uint32_t st  = smem_base + (cc & (NSs - 1)) * STG;
        const uint32_t saH = st;
        const uint32_t saL = st + 16384;
        const uint32_t sbH = st + (NSEG == 3 ? 32768 : 16384);
        const uint32_t sbL = st + 65536;

        uint32_t aH[2][4][4], bH[2][4][4];
#pragma unroll
        for (int t = 0; t < 4; ++t)
            ldsm4(aH[0][t], saH + SW128((aRow + t * 16) * 128 + aK * 2));
#pragma unroll
        for (int g = 0; g < 4; ++g)
            ldsm4(bH[0][g], sbH + SW128((bRow + g * 16) * 128 + bK * 2));

#pragma unroll
        for (int ks = 0; ks < KC / 16; ++ks) {
            const int kk  = ks * 16;
            const int cur = ks & 1, nxt = cur ^ 1;
            if (NSEG == 3) {
                uint32_t aL[4][4], bL[4][4];
#pragma unroll
                for (int t = 0; t < 4; ++t) {
                    ldsm4(aL[t], saL + SW128((aRow + t * 16) * 128 + (kk + aK) * 2));
#pragma unroll
                    for (int j = 0; j < 8; ++j)
                        mma16816(acc[t][j], aH[cur][t],
                                 bH[cur][j >> 1][(j & 1) * 2], bH[cur][j >> 1][(j & 1) * 2 + 1]);
                }
#pragma unroll
                for (int t = 0; t < 4; ++t) {
                    ldsm4(bL[t], sbL + SW128((bRow + t * 16) * 128 + (kk + bK) * 2));
#pragma unroll
                    for (int j = 0; j < 8; ++j)
                        mma16816(acc[t][j], aL[t],
                                 bH[cur][j >> 1][(j & 1) * 2], bH[cur][j >> 1][(j & 1) * 2 + 1]);
                }
#pragma unroll
                for (int t = 0; t < 4; ++t) {
                    if (ks < KC / 16 - 1) {
                        ldsm4(aH[nxt][t], saH + SW128((aRow + t * 16) * 128 + (kk + 16 + aK) * 2));
                        ldsm4(bH[nxt][t], sbH + SW128((bRow + t * 16) * 128 + (kk + 16 + bK) * 2));
                    }
#pragma unroll
                    for (int j = 0; j < 8; ++j)
                        mma16816(acc[t][j], aH[cur][t],
                                 bL[j >> 1][(j & 1) * 2], bL[j >> 1][(j & 1) * 2 + 1]);
                }
            } else {
#pragma unroll
                for (int t = 0; t < 4; ++t) {
                    if (ks < KC / 16 - 1) {
                        ldsm4(aH[nxt][t], saH + SW128((aRow + t * 16) * 128 + (kk + 16 + aK) * 2));
                        ldsm4(bH[nxt][t], sbH + SW128((bRow + t * 16) * 128 + (kk + 16 + bK) * 2));
                    }
#pragma unroll
                    for (int j = 0; j < 8; ++j)
                        mma16816(acc[t][j], aH[cur][t],
                                 bH[cur][j >> 1][(j & 1) * 2], bH[cur][j >> 1][(j & 1) * 2 + 1]);
                }
            }
        }
    }

    // ---- epilogue ----
    const int g8 = lid >> 2;
    const int tg = lid & 3;
#pragma unroll
    for (int t = 0; t < 4; ++t) {
        const int rbase = m0 + warp_m * 64 + t * 16 + g8;
#pragma unroll
        for (int j = 0; j < 8; ++j) {
            const int col = n0 + warp_n * 64 + j * 8 + tg * 2;
            if (EPI == 0) {
                float* p0 = Cf + (size_t)bz * sC + (size_t)rbase * ldc + col;
                float* p1 = p0 + (size_t)8 * ldc;
                ((float2*)p0)[0] = make_float2(acc[t][j][0], acc[t][j][1]);
                ((float2*)p1)[0] = make_float2(acc[t][j][2], acc[t][j][3]);
            } else {
                const float b0 = bias[col], b1 = bias[col + 1];
#pragma unroll
                for (int hrow = 0; hrow < 2; ++hrow) {
                    const int row = rbase + hrow * 8;
                    float v0 = acc[t][j][hrow * 2 + 0] + b0;
                    float v1 = acc[t][j][hrow * 2 + 1] + b1;
                    __half h0 = __float2half_rn(v0), h1 = __float2half_rn(v1);
                    __half l0 = __float2half_rn(v0 - __half2float(h0));
                    __half l1 = __float2half_rn(v1 - __half2float(h1));
                    *(__half2*)(Ch + (size_t)row * ldc + col)         = __halves2half2(h0, h1);
                    *(__half2*)(Ch + (size_t)row * ldc + loOff + col) = __halves2half2(l0, l1);
                }
            }
        }
    }
}

// ---------------------------------------------------------------------------
// fp32 [rows, C] -> fp16 [rows, 2C] hi|lo split
// ---------------------------------------------------------------------------
__global__ void split_rows(const float* __restrict__ in, __half* __restrict__ out,
                           int C, size_t total4)
{
    size_t i = (size_t)blockIdx.x * blockDim.x + threadIdx.x;
    if (i >= total4) return;
    const int c4 = C / 4;
    size_t r = i / c4;
    int c = (int)(i % c4) * 4;
    float4 v = ((const float4*)in)[i];
    __half h0 = __float2half_rn(v.x), h1 = __float2half_rn(v.y);
    __half h2 = __float2half_rn(v.z), h3 = __float2half_rn(v.w);
    __half l0 = __float2half_rn(v.x - __half2float(h0));
    __half l1 = __float2half_rn(v.y - __half2float(h1));
    __half l2 = __float2half_rn(v.z - __half2float(h2));
    __half l3 = __float2half_rn(v.w - __half2float(h3));
    __half* ph = out + r * (size_t)(2 * C) + c;
    ((__half2*)ph)[0] = __halves2half2(h0, h1);
    ((__half2*)ph)[1] = __halves2half2(h2, h3);
    __half* pl = ph + C;
    ((__half2*)pl)[0] = __halves2half2(l0, l1);
    ((__half2*)pl)[1] = __halves2half2(l2, l3);
}

// ---------------------------------------------------------------------------
// W transpose + hi/lo split: in [D, D] fp32 -> out [D, 2D] fp16
// ---------------------------------------------------------------------------
__global__ void transpose_split_w(const float* __restrict__ in, __half* __restrict__ out)
{
    __shared__ float t[32][33];
    const int r0 = blockIdx.x * 32, c0 = blockIdx.y * 32;
    const int tx = threadIdx.x, ty = threadIdx.y;  // 32 x 8
#pragma unroll
    for (int i = 0; i < 4; ++i)
        t[ty + i * 8][tx] = in[(size_t)(r0 + ty + i * 8) * D_ + c0 + tx];
    __syncthreads();
#pragma unroll
    for (int i = 0; i < 4; ++i) {
        const int cc = c0 + ty + i * 8;
        float v = t[tx][ty + i * 8];
        __half h = __float2half_rn(v);
        __half l = __float2half_rn(v - __half2float(h));
        out[(size_t)cc * (2 * D_) + r0 + tx]      = h;
        out[(size_t)cc * (2 * D_) + D_ + r0 + tx] = l;
    }
}

// ---------------------------------------------------------------------------
// Fused: candidate screen -> exact refine -> softmax -> sparse emission.
// ali holds APPROX scores on entry (dec_hi·keys_hi), final weights on exit.
// Candidates = entries within MARGIN of the approx row max; their scores are
// recomputed exactly as dot(dec_row fp32, keys_hi+keys_lo). All entries with
// true p > TAU are candidates by construction (MARGIN covers ln TAU + 2*delta).
// ---------------------------------------------------------------------------
__global__ __launch_bounds__(256)
void softmax_refine(const float* __restrict__ dec,
                    const __half* __restrict__ keys16,
                    float* __restrict__ ali,
                    int* __restrict__ sp_idx, float* __restrict__ sp_w,
                    int* __restrict__ sp_cnt)
{
    __shared__ float sdec[D_];
    __shared__ float srow[TK_];
    __shared__ int   cidx[TK_];
    __shared__ float red[8];
    __shared__ int   wsum[8];
    __shared__ int   carry;

    const int row = blockIdx.x;
    const int b   = row / TQ_;
    const int tid = threadIdx.x, lane = tid & 31, wid = tid >> 5;
    float* p = ali + (size_t)row * TK_;

    // dec row -> smem (fp32, exact A operand for refine)
    ((float4*)sdec)[tid] = ((const float4*)(dec + (size_t)row * D_))[tid];

    float4 v0 = ((const float4*)p)[tid];
    float4 v1 = ((const float4*)p)[tid + 256];
    ((float4*)srow)[tid]       = v0;
    ((float4*)srow)[tid + 256] = v1;

    // ---- approx row max ----
    float mx = fmaxf(fmaxf(fmaxf(v0.x, v0.y), fmaxf(v0.z, v0.w)),
                     fmaxf(fmaxf(v1.x, v1.y), fmaxf(v1.z, v1.w)));
#pragma unroll
    for (int o = 16; o > 0; o >>= 1) mx = fmaxf(mx, __shfl_xor_sync(~0u, mx, o));
    if (lane == 0) red[wid] = mx;
    __syncthreads();
    mx = red[0];
#pragma unroll
    for (int w = 1; w < 8; w++) mx = fmaxf(mx, red[w]);
    __syncthreads();

    const float thr = mx - MARGIN;

    // ---- candidate scan (deterministic k-order) ----
    if (tid == 0) carry = 0;
    __syncthreads();

    auto scan_cand = [&](float4 v, int kbase) {
        float vals[4] = {v.x, v.y, v.z, v.w};
        int cnt = 0;
#pragma unroll
        for (int i = 0; i < 4; ++i) cnt += (vals[i] > thr) ? 1 : 0;
        int inc = cnt;
#pragma unroll
        for (int o = 1; o < 32; o <<= 1) {
            int n = __shfl_up_sync(~0u, inc, o);
            if (lane >= o) inc += n;
        }
        if (lane == 31) wsum[wid] = inc;
        __syncthreads();
        int wbase = 0;
#pragma unroll
        for (int w = 0; w < 8; ++w) if (w < wid) wbase += wsum[w];
        int base = carry + wbase + inc - cnt;
        int o = 0;
#pragma unroll
        for (int i = 0; i < 4; ++i) {
            if (vals[i] > thr) { cidx[base + o] = kbase + i; ++o; }
        }
        __syncthreads();
        if (tid == 0) {
            int t = 0;
#pragma unroll
            for (int w = 0; w < 8; ++w) t += wsum[w];
            carry += t;
        }
        __syncthreads();
    };
    scan_cand(v0, tid * 4);
    scan_cand(v1, (tid + 256) * 4);

    const int nc = carry;

    // ---- exact refine: one warp per candidate ----
    for (int c = wid; c < nc; c += 8) {
        const int k = cidx[c];
        const __half* kr = keys16 + ((size_t)b * TK_ + k) * (2 * D_);
        float acc = 0.f;
        for (int d = lane; d < D_; d += 32) {
            float kv = __half2float(kr[d]) + __half2float(kr[D_ + d]);
            acc += sdec[d] * kv;
        }
#pragma unroll
        for (int o = 16; o > 0; o >>= 1) acc += __shfl_xor_sync(~0u, acc, o);
        if (lane == 0) srow[k] = acc;
    }
    __syncthreads();

    // ---- re-read (refined where candidate), true max, softmax ----
    v0 = ((const float4*)srow)[tid];
    v1 = ((const float4*)srow)[tid + 256];

    mx = fmaxf(fmaxf(fmaxf(v0.x, v0.y), fmaxf(v0.z, v0.w)),
               fmaxf(fmaxf(v1.x, v1.y), fmaxf(v1.z, v1.w)));
#pragma unroll
    for (int o = 16; o > 0; o >>= 1) mx = fmaxf(mx, __shfl_xor_sync(~0u, mx, o));
    if (lane == 0) red[wid] = mx;
    __syncthreads();
    mx = red[0];
#pragma unroll
    for (int w = 1; w < 8; w++) mx = fmaxf(mx, red[w]);
    __syncthreads();

    v0.x = __expf(v0.x - mx); v0.y = __expf(v0.y - mx);
    v0.z = __expf(v0.z - mx); v0.w = __expf(v0.w - mx);
    v1.x = __expf(v1.x - mx); v1.y = __expf(v1.y - mx);
    v1.z = __expf(v1.z - mx); v1.w = __expf(v1.w - mx);

    float s = v0.x + v0.y + v0.z + v0.w + v1.x + v1.y + v1.z + v1.w;
#pragma unroll
    for (int o = 16; o > 0; o >>= 1) s += __shfl_xor_sync(~0u, s, o);
    if (lane == 0) red[wid] = s;
    __syncthreads();
    s = red[0] + red[1] + red[2] + red[3] + red[4] + red[5] + red[6] + red[7];
    __syncthreads();

    const float inv = 1.0f / s;
    v0.x *= inv; v0.y *= inv; v0.z *= inv; v0.w *= inv;
    v1.x *= inv; v1.y *= inv; v1.z *= inv; v1.w *= inv;

    ((float4*)p)[tid]       = v0;
    ((float4*)p)[tid + 256] = v1;

    // ---- sparse emission (p > TAU), deterministic order ----
    if (tid == 0) carry = 0;
    __syncthreads();

    int* rIdx = sp_idx + (size_t)row * CAP;
    float* rW = sp_w   + (size_t)row * CAP;

    auto emit = [&](float4 v, int kbase) {
        float vals[4] = {v.x, v.y, v.z, v.w};
        int cnt = 0;
#pragma unroll
        for (int i = 0; i < 4; ++i) cnt += (vals[i] > TAU) ? 1 : 0;
        int inc = cnt;
#pragma unroll
        for (int o = 1; o < 32; o <<= 1) {
            int n = __shfl_up_sync(~0u, inc, o);
            if (lane >= o) inc += n;
        }
        if (lane == 31) wsum[wid] = inc;
        __syncthreads();
        int wbase = 0;
#pragma unroll
        for (int w = 0; w < 8; ++w) if (w < wid) wbase += wsum[w];
        int base = carry + wbase + inc - cnt;
        int o = 0;
#pragma unroll
        for (int i = 0; i < 4; ++i) {
            if (vals[i] > TAU) {
                int pos = base + o; ++o;
                if (pos < CAP) { rIdx[pos] = kbase + i; rW[pos] = vals[i]; }
            }
        }
        __syncthreads();
        if (tid == 0) {
            int t = 0;
#pragma unroll
            for (int w = 0; w < 8; ++w) t += wsum[w];
            carry += t;
        }
        __syncthreads();
    };
    emit(v0, tid * 4);
    emit(v1, (tid + 256) * 4);

    if (tid == 0) sp_cnt[row] = carry;
}

// ---------------------------------------------------------------------------
// Sparse context: ctx[row,:] = sum_e w_e * enc[b, k_e, :]  (fp32 exact).
// Dense fallback (exact) if count > CAP.
// ---------------------------------------------------------------------------
__global__ __launch_bounds__(256)
void ctx_sparse(const float* __restrict__ enc, const float* __restrict__ ali,
                const int* __restrict__ sp_cnt, const int* __restrict__ sp_idx,
                const float* __restrict__ sp_w, float* __restrict__ ctx)
{
    const int row = blockIdx.x;
    const int b   = row / TQ_;
    const int tid = threadIdx.x;
    const float* encB = enc + (size_t)b * TK_ * D_;

    float4 acc = make_float4(0.f, 0.f, 0.f, 0.f);
    const int cnt = sp_cnt[row];

    if (cnt <= CAP) {
        const int* rIdx = sp_idx + (size_t)row * CAP;
        const float* rW = sp_w + (size_t)row * CAP;
        for (int e = 0; e < cnt; ++e) {
            const int k = rIdx[e];
            const float w = rW[e];
            float4 ev = ((const float4*)(encB + (size_t)k * D_))[tid];
            acc.x += w * ev.x; acc.y += w * ev.y;
            acc.z += w * ev.z; acc.w += w * ev.w;
        }
    } else {
        const float* arow = ali + (size_t)row * TK_;
        for (int k = 0; k < TK_; ++k) {
            const float w = arow[k];
            if (w > TAU) {
                float4 ev = ((const float4*)(encB + (size_t)k * D_))[tid];
                acc.x += w * ev.x; acc.y += w * ev.y;
                acc.z += w * ev.z; acc.w += w * ev.w;
            }
        }
    }
    ((float4*)(ctx + (size_t)row * D_))[tid] = acc;
}

// ---------------------------------------------------------------------------
// kernel_launch — single stream.
// dec/enc/W splits -> keys GEMM (3-seg) -> approx score GEMM (1-seg)
//   -> fused refine+softmax+sparse -> sparse context gather
// ---------------------------------------------------------------------------
extern "C" void kernel_launch(void* const* d_in, const int* in_sizes, int n_in,
                              void* d_out, int out_size)
{
    (void)in_sizes; (void)n_in; (void)out_size;

    const float* dec = (const float*)d_in[0];
    const float* enc = (const float*)d_in[1];
    const float* wk  = (const float*)d_in[2];
    const float* wb  = (const float*)d_in[3];

    float* ctx = (float*)d_out;                            // [B, TQ, D]
    float* ali = (float*)d_out + (size_t)B_ * TQ_ * D_;    // [B, TQ, TK]

    __half *dec16, *enc16, *keys16, *w16T;
    int *sp_idx, *sp_cnt;
    float *sp_w;
    cudaGetSymbolAddress((void**)&dec16,  g_dec16);
    cudaGetSymbolAddress((void**)&enc16,  g_enc16);
    cudaGetSymbolAddress((void**)&keys16, g_keys16);
    cudaGetSymbolAddress((void**)&w16T,   g_w16T);
    cudaGetSymbolAddress((void**)&sp_idx, g_sp_idx);
    cudaGetSymbolAddress((void**)&sp_w,   g_sp_w);
    cudaGetSymbolAddress((void**)&sp_cnt, g_sp_cnt);

    cudaFuncSetAttribute(gemm_hmma<0,1>, cudaFuncAttributeMaxDynamicSharedMemorySize, GEMM_SMEM);
    cudaFuncSetAttribute(gemm_hmma<1,3>, cudaFuncAttributeMaxDynamicSharedMemorySize, GEMM_SMEM);

    // --- conversions ---
    {
        size_t t4 = (size_t)B_ * TQ_ * D_ / 4;
        split_rows<<<(unsigned)((t4 + 255) / 256), 256>>>(dec, dec16, D_, t4);
        split_rows<<<(unsigned)((t4 + 255) / 256), 256>>>(enc, enc16, D_, t4);
    }
    transpose_split_w<<<dim3(D_ / 32, D_ / 32), dim3(32, 8)>>>(wk, w16T);

    // --- keys = enc·W + bias -> keys16 hi/lo (fused 3-seg) ---
    gemm_hmma<1,3><<<dim3(D_ / BN, (B_ * TK_) / BM, 1), 256, GEMM_SMEM>>>(
        enc16, w16T, wb, nullptr, keys16,
        2 * D_, 2 * D_, 2 * D_, D_, D_, 0, 0, 0);

    // --- approx score = dec_hi·keys_hi^T -> ali fp32 (batched, 1-seg) ---
    gemm_hmma<0,1><<<dim3(TK_ / BN, TQ_ / BM, B_), 256, GEMM_SMEM>>>(
        dec16, keys16, nullptr, ali, nullptr,
        2 * D_, 2 * D_, TK_, D_, 0,
        (size_t)TQ_ * 2 * D_, (size_t)TK_ * 2 * D_, (size_t)TQ_ * TK_);

    // --- fused candidate refine + softmax + sparse emission ---
    softmax_refine<<<B_ * TQ_, 256>>>(dec, keys16, ali, sp_idx, sp_w, sp_cnt);

    // --- context = sparse gather over enc (fp32 exact) ---
    ctx_sparse<<<B_ * TQ_, 256>>>(enc, ali, sp_cnt, sp_idx, sp_w, ctx);
}

// round 17
// speedup vs baseline: 1.5660x; 1.0481x over previous
#include <cuda_runtime.h>
#include <cuda_fp16.h>
#include <cstdint>
#include <cstddef>

// Problem dims (fixed)
#define B_   16
#define TQ_  2048
#define TK_  2048
#define D_   1024

#define CAP     64          // sparse-context list capacity (p > TAU)
#define TAU     1e-8f
#define MARGIN  23.0f       // candidate screen margin (18.42 + guard)

// ---------------------------------------------------------------------------
// Scratch (static __device__ arrays = sanctioned no-alloc scratch)
// g_dec16: dec hi-only [B*TQ, D].
// g_enc16: enc hi|lo [B*TK, 2D] for keys GEMM; REUSED afterwards as the fp16
//          approx-score buffer [B*TQ, TK] (same element count, enc dead then).
// ---------------------------------------------------------------------------
__device__ __half g_dec16 [(size_t)B_ * TQ_ * D_];       // [B*TQ, D] hi only
__device__ __half g_enc16 [(size_t)B_ * TK_ * 2 * D_];   // [B*TK, 2D] / score16
__device__ __half g_keys16[(size_t)B_ * TK_ * 2 * D_];   // [B*TK, 2D]
__device__ __half g_w16T  [(size_t)D_ * 2 * D_];         // [D, 2D]
__device__ int    g_sp_idx[(size_t)B_ * TQ_ * CAP];
__device__ float  g_sp_w  [(size_t)B_ * TQ_ * CAP];
__device__ int    g_sp_cnt[(size_t)B_ * TQ_];

__device__ __forceinline__ uint32_t smem_u32(const void* p) {
    return (uint32_t)__cvta_generic_to_shared(p);
}

#define SW128(x) ((x) ^ (((x) >> 3) & 0x70))

// ---------------------------------------------------------------------------
// HMMA GEMM, fused hi/lo segments (R13 proven inner loop).
//   NSEG=3: C = hiA·hiB^T + loA·hiB^T + hiA·loB^T; stage 96KB, NS=2.
//   NSEG=1: plain C = A·B^T (hi halves); stage 48KB, NS=4.
// CTA tile 128x256, K-chunk 64, 8 warps (2M x 4N), warp tile 64x64.
// EPI=0: fp32 C. EPI=1: bias + hi/lo fp16 out. EPI=2: plain fp16 out.
// ---------------------------------------------------------------------------
#define BM  128
#define BN  256
#define KC  64
static constexpr int GEMM_SMEM = 196608;

__device__ __forceinline__ void cpa16(uint32_t dst, const void* src) {
    asm volatile("cp.async.cg.shared.global [%0], [%1], 16;" :: "r"(dst), "l"(src));
}

__device__ __forceinline__ void ldsm4(uint32_t* r, uint32_t addr) {
    asm volatile("ldmatrix.sync.aligned.m8n8.x4.shared.b16 {%0,%1,%2,%3}, [%4];"
                 : "=r"(r[0]), "=r"(r[1]), "=r"(r[2]), "=r"(r[3]) : "r"(addr));
}

__device__ __forceinline__ void mma16816(float* d, const uint32_t* a,
                                         const uint32_t b0, const uint32_t b1) {
    asm volatile("mma.sync.aligned.m16n8k16.row.col.f32.f16.f16.f32 "
                 "{%0,%1,%2,%3}, {%4,%5,%6,%7}, {%8,%9}, {%0,%1,%2,%3};"
                 : "+f"(d[0]), "+f"(d[1]), "+f"(d[2]), "+f"(d[3])
                 : "r"(a[0]), "r"(a[1]), "r"(a[2]), "r"(a[3]), "r"(b0), "r"(b1));
}

template<int NSEG>
__device__ __forceinline__ void load_chunk(const __half* A, const __half* Bm,
                                           int lda, int ldb, int m0, int n0,
                                           int K, int kin, uint32_t stage_base,
                                           int tid) {
    const int ka = kin * KC;
    const uint32_t saH = stage_base;
    const uint32_t saL = stage_base + 16384;
    const uint32_t sbH = stage_base + (NSEG == 3 ? 32768 : 16384);
    const uint32_t sbL = stage_base + 65536;
#pragma unroll
    for (int it = 0; it < (BM * 8) / 256; ++it) {
        int idx = tid + it * 256;
        int row = idx >> 3, c16 = idx & 7;
        const __half* g = A + (size_t)(m0 + row) * lda + ka + c16 * 8;
        uint32_t sw = SW128(row * 128 + c16 * 16);
        cpa16(saH + sw, g);
        if (NSEG == 3) cpa16(saL + sw, g + K);
    }
#pragma unroll
    for (int it = 0; it < (BN * 8) / 256; ++it) {
        int idx = tid + it * 256;
        int row = idx >> 3, c16 = idx & 7;
        const __half* g = Bm + (size_t)(n0 + row) * ldb + ka + c16 * 8;
        uint32_t sw = SW128(row * 128 + c16 * 16);
        cpa16(sbH + sw, g);
        if (NSEG == 3) cpa16(sbL + sw, g + K);
    }
}

template<int EPI, int NSEG>
__global__ __launch_bounds__(256, 1)
void gemm_hmma(const __half* __restrict__ A, const __half* __restrict__ Bm,
               const float* __restrict__ bias,
               float* __restrict__ Cf, __half* __restrict__ Ch,
               int lda, int ldb, int ldc, int K, int loOff,
               size_t sA, size_t sB, size_t sC)
{
    constexpr int NSs = (NSEG == 3) ? 2 : 4;
    constexpr int STG = (NSEG == 3) ? 98304 : 49152;

    extern __shared__ __align__(1024) char smem[];
    const uint32_t smem_base = smem_u32(smem);
    const int tid = threadIdx.x, wid = tid >> 5, lid = tid & 31;
    const int bz = blockIdx.z;
    A  += (size_t)bz * sA;
    Bm += (size_t)bz * sB;

    const int m0 = blockIdx.y * BM;
    const int n0 = blockIdx.x * BN;

    const int nk = K / KC;

    const int warp_m = wid & 1;
    const int warp_n = wid >> 1;

    float acc[4][8][4];
#pragma unroll
    for (int t = 0; t < 4; ++t)
#pragma unroll
        for (int j = 0; j < 8; ++j)
#pragma unroll
            for (int c = 0; c < 4; ++c) acc[t][j][c] = 0.f;

    const int aRow = warp_m * 64 + (lid & 15);
    const int aK   = (lid & 16) >> 1;
    const int bRow = warp_n * 64 + (lid & 7) + ((lid & 16) >> 1);
    const int bK   = (lid & 8);

#pragma unroll
    for (int i = 0; i < NSs - 1; ++i) {
        if (i < nk) load_chunk<NSEG>(A, Bm, lda, ldb, m0, n0, K, i,
                                     smem_base + i * STG, tid);
        asm volatile("cp.async.commit_group;" ::: "memory");
    }

    for (int cc = 0; cc < nk; ++cc) {
        asm volatile("cp.async.wait_group %0;" :: "n"(NSs - 2));
        __syncthreads();

        {
            const int cl = cc + NSs - 1;
            if (cl < nk)
                load_chunk<NSEG>(A, Bm, lda, ldb, m0, n0, K, cl,
                                 smem_base + (cl & (NSs - 1)) * STG, tid);
            asm volatile("cp.async.commit_group;" ::: "memory");
        }

        const uint32_t st  = smem_base + (cc & (NSs - 1)) * STG;
        const uint32_t saH = st;
        const uint32_t saL = st + 16384;
        const uint32_t sbH = st + (NSEG == 3 ? 32768 : 16384);
        const uint32_t sbL = st + 65536;

        uint32_t aH[2][4][4], bH[2][4][4];
#pragma unroll
        for (int t = 0; t < 4; ++t)
            ldsm4(aH[0][t], saH + SW128((aRow + t * 16) * 128 + aK * 2));
#pragma unroll
        for (int g = 0; g < 4; ++g)
            ldsm4(bH[0][g], sbH + SW128((bRow + g * 16) * 128 + bK * 2));

#pragma unroll
        for (int ks = 0; ks < KC / 16; ++ks) {
            const int kk  = ks * 16;
            const int cur = ks & 1, nxt = cur ^ 1;
            if (NSEG == 3) {
                uint32_t aL[4][4], bL[4][4];
#pragma unroll
                for (int t = 0; t < 4; ++t) {
                    ldsm4(aL[t], saL + SW128((aRow + t * 16) * 128 + (kk + aK) * 2));
#pragma unroll
                    for (int j = 0; j < 8; ++j)
                        mma16816(acc[t][j], aH[cur][t],
                                 bH[cur][j >> 1][(j & 1) * 2], bH[cur][j >> 1][(j & 1) * 2 + 1]);
                }
#pragma unroll
                for (int t = 0; t < 4; ++t) {
                    ldsm4(bL[t], sbL + SW128((bRow + t * 16) * 128 + (kk + bK) * 2));
#pragma unroll
                    for (int j = 0; j < 8; ++j)
                        mma16816(acc[t][j], aL[t],
                                 bH[cur][j >> 1][(j & 1) * 2], bH[cur][j >> 1][(j & 1) * 2 + 1]);
                }
#pragma unroll
                for (int t = 0; t < 4; ++t) {
                    if (ks < KC / 16 - 1) {
                        ldsm4(aH[nxt][t], saH + SW128((aRow + t * 16) * 128 + (kk + 16 + aK) * 2));
                        ldsm4(bH[nxt][t], sbH + SW128((bRow + t * 16) * 128 + (kk + 16 + bK) * 2));
                    }
#pragma unroll
                    for (int j = 0; j < 8; ++j)
                        mma16816(acc[t][j], aH[cur][t],
                                 bL[j >> 1][(j & 1) * 2], bL[j >> 1][(j & 1) * 2 + 1]);
                }
            } else {
#pragma unroll
                for (int t = 0; t < 4; ++t) {
                    if (ks < KC / 16 - 1) {
                        ldsm4(aH[nxt][t], saH + SW128((aRow + t * 16) * 128 + (kk + 16 + aK) * 2));
                        ldsm4(bH[nxt][t], sbH + SW128((bRow + t * 16) * 128 + (kk + 16 + bK) * 2));
                    }
#pragma unroll
                    for (int j = 0; j < 8; ++j)
                        mma16816(acc[t][j], aH[cur][t],
                                 bH[cur][j >> 1][(j & 1) * 2], bH[cur][j >> 1][(j & 1) * 2 + 1]);
                }
            }
        }
    }

    // ---- epilogue ----
    const int g8 = lid >> 2;
    const int tg = lid & 3;
#pragma unroll
    for (int t = 0; t < 4; ++t) {
        const int rbase = m0 + warp_m * 64 + t * 16 + g8;
#pragma unroll
        for (int j = 0; j < 8; ++j) {
            const int col = n0 + warp_n * 64 + j * 8 + tg * 2;
            if (EPI == 0) {
                float* p0 = Cf + (size_t)bz * sC + (size_t)rbase * ldc + col;
                float* p1 = p0 + (size_t)8 * ldc;
                ((float2*)p0)[0] = make_float2(acc[t][j][0], acc[t][j][1]);
                ((float2*)p1)[0] = make_float2(acc[t][j][2], acc[t][j][3]);
            } else if (EPI == 2) {
                __half* pc = Ch + (size_t)bz * sC + (size_t)rbase * ldc + col;
                *(__half2*)pc = __halves2half2(__float2half_rn(acc[t][j][0]),
                                               __float2half_rn(acc[t][j][1]));
                *(__half2*)(pc + (size_t)8 * ldc) =
                    __halves2half2(__float2half_rn(acc[t][j][2]),
                                   __float2half_rn(acc[t][j][3]));
            } else {
                const float b0 = bias[col], b1 = bias[col + 1];
#pragma unroll
                for (int hrow = 0; hrow < 2; ++hrow) {
                    const int row = rbase + hrow * 8;
                    float v0 = acc[t][j][hrow * 2 + 0] + b0;
                    float v1 = acc[t][j][hrow * 2 + 1] + b1;
                    __half h0 = __float2half_rn(v0), h1 = __float2half_rn(v1);
                    __half l0 = __float2half_rn(v0 - __half2float(h0));
                    __half l1 = __float2half_rn(v1 - __half2float(h1));
                    *(__half2*)(Ch + (size_t)row * ldc + col)         = __halves2half2(h0, h1);
                    *(__half2*)(Ch + (size_t)row * ldc + loOff + col) = __halves2half2(l0, l1);
                }
            }
        }
    }
}

// ---------------------------------------------------------------------------
// fp32 -> fp16 hi-only (linear; used for dec)
// ---------------------------------------------------------------------------
__global__ void split_hi(const float* __restrict__ in, __half* __restrict__ out,
                         size_t total4)
{
    size_t i = (size_t)blockIdx.x * blockDim.x + threadIdx.x;
    if (i >= total4) return;
    float4 v = ((const float4*)in)[i];
    __half2 a = __halves2half2(__float2half_rn(v.x), __float2half_rn(v.y));
    __half2 b = __halves2half2(__float2half_rn(v.z), __float2half_rn(v.w));
    ((__half2*)(out + i * 4))[0] = a;
    ((__half2*)(out + i * 4))[1] = b;
}

// ---------------------------------------------------------------------------
// fp32 [rows, C] -> fp16 [rows, 2C] hi|lo split (enc)
// ---------------------------------------------------------------------------
__global__ void split_rows(const float* __restrict__ in, __half* __restrict__ out,
                           int C, size_t total4)
{
    size_t i = (size_t)blockIdx.x * blockDim.x + threadIdx.x;
    if (i >= total4) return;
    const int c4 = C / 4;
    size_t r = i / c4;
    int c = (int)(i % c4) * 4;
    float4 v = ((const float4*)in)[i];
    __half h0 = __float2half_rn(v.x), h1 = __float2half_rn(v.y);
    __half h2 = __float2half_rn(v.z), h3 = __float2half_rn(v.w);
    __half l0 = __float2half_rn(v.x - __half2float(h0));
    __half l1 = __float2half_rn(v.y - __half2float(h1));
    __half l2 = __float2half_rn(v.z - __half2float(h2));
    __half l3 = __float2half_rn(v.w - __half2float(h3));
    __half* ph = out + r * (size_t)(2 * C) + c;
    ((__half2*)ph)[0] = __halves2half2(h0, h1);
    ((__half2*)ph)[1] = __halves2half2(h2, h3);
    __half* pl = ph + C;
    ((__half2*)pl)[0] = __halves2half2(l0, l1);
    ((__half2*)pl)[1] = __halves2half2(l2, l3);
}

// ---------------------------------------------------------------------------
// W transpose + hi/lo split: in [D, D] fp32 -> out [D, 2D] fp16
// ---------------------------------------------------------------------------
__global__ void transpose_split_w(const float* __restrict__ in, __half* __restrict__ out)
{
    __shared__ float t[32][33];
    const int r0 = blockIdx.x * 32, c0 = blockIdx.y * 32;
    const int tx = threadIdx.x, ty = threadIdx.y;  // 32 x 8
#pragma unroll
    for (int i = 0; i < 4; ++i)
        t[ty + i * 8][tx] = in[(size_t)(r0 + ty + i * 8) * D_ + c0 + tx];
    __syncthreads();
#pragma unroll
    for (int i = 0; i < 4; ++i) {
        const int cc = c0 + ty + i * 8;
        float v = t[tx][ty + i * 8];
        __half h = __float2half_rn(v);
        __half l = __float2half_rn(v - __half2float(h));
        out[(size_t)cc * (2 * D_) + r0 + tx]      = h;
        out[(size_t)cc * (2 * D_) + D_ + r0 + tx] = l;
    }
}

// ---------------------------------------------------------------------------
// Fused: candidate screen (fp16 approx scores) -> exact refine -> softmax ->
// fp32 alignment out + sparse (idx, weight) emission.
// ---------------------------------------------------------------------------
__global__ __launch_bounds__(256)
void softmax_refine(const float* __restrict__ dec,
                    const __half* __restrict__ keys16,
                    const __half* __restrict__ score16,
                    float* __restrict__ ali,
                    int* __restrict__ sp_idx, float* __restrict__ sp_w,
                    int* __restrict__ sp_cnt)
{
    __shared__ float sdec[D_];
    __shared__ float srow[TK_];
    __shared__ int   cidx[TK_];
    __shared__ float red[8];
    __shared__ int   wsum[8];
    __shared__ int   carry;

    const int row = blockIdx.x;
    const int b   = row / TQ_;
    const int tid = threadIdx.x, lane = tid & 31, wid = tid >> 5;

    // dec row -> smem fp32 (exact A operand for refine)
    ((float4*)sdec)[tid] = ((const float4*)(dec + (size_t)row * D_))[tid];

    // approx scores: 8 halves per thread
    float v[8];
    {
        uint4 raw = ((const uint4*)(score16 + (size_t)row * TK_))[tid];
        const __half2* hp = (const __half2*)&raw;
#pragma unroll
        for (int i = 0; i < 4; ++i) {
            float2 f = __half22float2(hp[i]);
            v[2 * i]     = f.x;
            v[2 * i + 1] = f.y;
        }
#pragma unroll
        for (int i = 0; i < 8; ++i) srow[tid * 8 + i] = v[i];
    }

    // ---- approx row max ----
    float mx = v[0];
#pragma unroll
    for (int i = 1; i < 8; ++i) mx = fmaxf(mx, v[i]);
#pragma unroll
    for (int o = 16; o > 0; o >>= 1) mx = fmaxf(mx, __shfl_xor_sync(~0u, mx, o));
    if (lane == 0) red[wid] = mx;
    __syncthreads();
    mx = red[0];
#pragma unroll
    for (int w = 1; w < 8; w++) mx = fmaxf(mx, red[w]);
    __syncthreads();

    const float thr = mx - MARGIN;

    // ---- candidate scan (deterministic k-order) ----
    if (tid == 0) carry = 0;
    __syncthreads();

    auto scan_cand = [&](const float* vals, int kbase) {
        int cnt = 0;
#pragma unroll
        for (int i = 0; i < 4; ++i) cnt += (vals[i] > thr) ? 1 : 0;
        int inc = cnt;
#pragma unroll
        for (int o = 1; o < 32; o <<= 1) {
            int n = __shfl_up_sync(~0u, inc, o);
            if (lane >= o) inc += n;
        }
        if (lane == 31) wsum[wid] = inc;
        __syncthreads();
        int wbase = 0;
#pragma unroll
        for (int w = 0; w < 8; ++w) if (w < wid) wbase += wsum[w];
        int base = carry + wbase + inc - cnt;
        int o = 0;
#pragma unroll
        for (int i = 0; i < 4; ++i) {
            if (vals[i] > thr) { cidx[base + o] = kbase + i; ++o; }
        }
        __syncthreads();
        if (tid == 0) {
            int t = 0;
#pragma unroll
            for (int w = 0; w < 8; ++w) t += wsum[w];
            carry += t;
        }
        __syncthreads();
    };
    scan_cand(v,     tid * 8);
    scan_cand(v + 4, tid * 8 + 4);

    const int nc = carry;

    // ---- exact refine: one warp per candidate, __half2 key loads ----
    for (int c = wid; c < nc; c += 8) {
        const int k = cidx[c];
        const __half2* krH = (const __half2*)(keys16 + ((size_t)b * TK_ + k) * (2 * D_));
        const __half2* krL = krH + D_ / 2;
        float acc = 0.f;
        for (int d = lane; d < D_ / 2; d += 32) {
            float2 h = __half22float2(krH[d]);
            float2 l = __half22float2(krL[d]);
            acc += sdec[2 * d] * (h.x + l.x) + sdec[2 * d + 1] * (h.y + l.y);
        }
#pragma unroll
        for (int o = 16; o > 0; o >>= 1) acc += __shfl_xor_sync(~0u, acc, o);
        if (lane == 0) srow[k] = acc;
    }
    __syncthreads();

    // ---- re-read (refined where candidate), true max, softmax ----
#pragma unroll
    for (int i = 0; i < 8; ++i) v[i] = srow[tid * 8 + i];

    mx = v[0];
#pragma unroll
    for (int i = 1; i < 8; ++i) mx = fmaxf(mx, v[i]);
#pragma unroll
    for (int o = 16; o > 0; o >>= 1) mx = fmaxf(mx, __shfl_xor_sync(~0u, mx, o));
    if (lane == 0) red[wid] = mx;
    __syncthreads();
    mx = red[0];
#pragma unroll
    for (int w = 1; w < 8; w++) mx = fmaxf(mx, red[w]);
    __syncthreads();

    float s = 0.f;
#pragma unroll
    for (int i = 0; i < 8; ++i) { v[i] = __expf(v[i] - mx); s += v[i]; }
#pragma unroll
    for (int o = 16; o > 0; o >>= 1) s += __shfl_xor_sync(~0u, s, o);
    if (lane == 0) red[wid] = s;
    __syncthreads();
    s = red[0] + red[1] + red[2] + red[3] + red[4] + red[5] + red[6] + red[7];
    __syncthreads();

    const float inv = 1.0f / s;
#pragma unroll
    for (int i = 0; i < 8; ++i) v[i] *= inv;

    float* p = ali + (size_t)row * TK_;
    ((float4*)p)[tid * 2]     = make_float4(v[0], v[1], v[2], v[3]);
    ((float4*)p)[tid * 2 + 1] = make_float4(v[4], v[5], v[6], v[7]);

    // ---- sparse emission (p > TAU), deterministic order ----
    if (tid == 0) carry = 0;
    __syncthreads();

    int* rIdx = sp_idx + (size_t)row * CAP;
    float* rW = sp_w   + (size_t)row * CAP;

    auto emit = [&](const float* vals, int kbase) {
        int cnt = 0;
#pragma unroll
        for (int i = 0; i < 4; ++i) cnt += (vals[i] > TAU) ? 1 : 0;
        int inc = cnt;
#pragma unroll
        for (int o = 1; o < 32; o <<= 1) {
            int n = __shfl_up_sync(~0u, inc, o);
            if (lane >= o) inc += n;
        }
        if (lane == 31) wsum[wid] = inc;
        __syncthreads();
        int wbase = 0;
#pragma unroll
        for (int w = 0; w < 8; ++w) if (w < wid) wbase += wsum[w];
        int base = carry + wbase + inc - cnt;
        int o = 0;
#pragma unroll
        for (int i = 0; i < 4; ++i) {
            if (vals[i] > TAU) {
                int pos = base + o; ++o;
                if (pos < CAP) { rIdx[pos] = kbase + i; rW[pos] = vals[i]; }
            }
        }
        __syncthreads();
        if (tid == 0) {
            int t = 0;
#pragma unroll
            for (int w = 0; w < 8; ++w) t += wsum[w];
            carry += t;
        }
        __syncthreads();
    };
    emit(v,     tid * 8);
    emit(v + 4, tid * 8 + 4);

    if (tid == 0) sp_cnt[row] = carry;
}

// ---------------------------------------------------------------------------
// Sparse context: ctx[row,:] = sum_e w_e * enc[b, k_e, :]  (fp32 exact).
// Dense fallback (exact) if count > CAP.
// ---------------------------------------------------------------------------
__global__ __launch_bounds__(256)
void ctx_sparse(const float* __restrict__ enc, const float* __restrict__ ali,
                const int* __restrict__ sp_cnt, const int* __restrict__ sp_idx,
                const float* __restrict__ sp_w, float* __restrict__ ctx)
{
    const int row = blockIdx.x;
    const int b   = row / TQ_;
    const int tid = threadIdx.x;
    const float* encB = enc + (size_t)b * TK_ * D_;

    float4 acc = make_float4(0.f, 0.f, 0.f, 0.f);
    const int cnt = sp_cnt[row];

    if (cnt <= CAP) {
        const int* rIdx = sp_idx + (size_t)row * CAP;
        const float* rW = sp_w + (size_t)row * CAP;
        for (int e = 0; e < cnt; ++e) {
            const int k = rIdx[e];
            const float w = rW[e];
            float4 ev = ((const float4*)(encB + (size_t)k * D_))[tid];
            acc.x += w * ev.x; acc.y += w * ev.y;
            acc.z += w * ev.z; acc.w += w * ev.w;
        }
    } else {
        const float* arow = ali + (size_t)row * TK_;
        for (int k = 0; k < TK_; ++k) {
            const float w = arow[k];
            if (w > TAU) {
                float4 ev = ((const float4*)(encB + (size_t)k * D_))[tid];
                acc.x += w * ev.x; acc.y += w * ev.y;
                acc.z += w * ev.z; acc.w += w * ev.w;
            }
        }
    }
    ((float4*)(ctx + (size_t)row * D_))[tid] = acc;
}

// ---------------------------------------------------------------------------
// kernel_launch — single stream.
// dec hi-split, enc hi/lo split, W split -> keys GEMM (3-seg)
//   -> approx score GEMM (1-seg, fp16 out into reused enc16 buffer)
//   -> fused refine+softmax+sparse -> sparse context gather
// ---------------------------------------------------------------------------
extern "C" void kernel_launch(void* const* d_in, const int* in_sizes, int n_in,
                              void* d_out, int out_size)
{
    (void)in_sizes; (void)n_in; (void)out_size;

    const float* dec = (const float*)d_in[0];
    const float* enc = (const float*)d_in[1];
    const float* wk  = (const float*)d_in[2];
    const float* wb  = (const float*)d_in[3];

    float* ctx = (float*)d_out;                            // [B, TQ, D]
    float* ali = (float*)d_out + (size_t)B_ * TQ_ * D_;    // [B, TQ, TK]

    __half *dec16, *enc16, *keys16, *w16T;
    int *sp_idx, *sp_cnt;
    float *sp_w;
    cudaGetSymbolAddress((void**)&dec16,  g_dec16);
    cudaGetSymbolAddress((void**)&enc16,  g_enc16);
    cudaGetSymbolAddress((void**)&keys16, g_keys16);
    cudaGetSymbolAddress((void**)&w16T,   g_w16T);
    cudaGetSymbolAddress((void**)&sp_idx, g_sp_idx);
    cudaGetSymbolAddress((void**)&sp_w,   g_sp_w);
    cudaGetSymbolAddress((void**)&sp_cnt, g_sp_cnt);

    __half* score16 = enc16;   // enc16 is dead after the keys GEMM; reuse.

    cudaFuncSetAttribute(gemm_hmma<2,1>, cudaFuncAttributeMaxDynamicSharedMemorySize, GEMM_SMEM);
    cudaFuncSetAttribute(gemm_hmma<1,3>, cudaFuncAttributeMaxDynamicSharedMemorySize, GEMM_SMEM);

    // --- conversions ---
    {
        size_t t4 = (size_t)B_ * TQ_ * D_ / 4;
        split_hi<<<(unsigned)((t4 + 255) / 256), 256>>>(dec, dec16, t4);
        split_rows<<<(unsigned)((t4 + 255) / 256), 256>>>(enc, enc16, D_, t4);
    }
    transpose_split_w<<<dim3(D_ / 32, D_ / 32), dim3(32, 8)>>>(wk, w16T);

    // --- keys = enc·W + bias -> keys16 hi/lo (fused 3-seg) ---
    gemm_hmma<1,3><<<dim3(D_ / BN, (B_ * TK_) / BM, 1), 256, GEMM_SMEM>>>(
        enc16, w16T, wb, nullptr, keys16,
        2 * D_, 2 * D_, 2 * D_, D_, D_, 0, 0, 0);

    // --- approx score = dec_hi·keys_hi^T -> score16 fp16 (batched, 1-seg) ---
    gemm_hmma<2,1><<<dim3(TK_ / BN, TQ_ / BM, B_), 256, GEMM_SMEM>>>(
        dec16, keys16, nullptr, nullptr, score16,
        D_, 2 * D_, TK_, D_, 0,
        (size_t)TQ_ * D_, (size_t)TK_ * 2 * D_, (size_t)TQ_ * TK_);

    // --- fused candidate refine + softmax + sparse emission ---
    softmax_refine<<<B_ * TQ_, 256>>>(dec, keys16, score16, ali,
                                      sp_idx, sp_w, sp_cnt);

    // --- context = sparse gather over enc (fp32 exact) ---
    ctx_sparse<<<B_ * TQ_, 256>>>(enc, ali, sp_cnt, sp_idx, sp_w, ctx);
}